// round 6
// baseline (speedup 1.0000x reference)
#include <cuda_runtime.h>
#include <cuda_bf16.h>
#include <math_constants.h>
#include <stdint.h>

#define BATCH 4
#define NTOK 4096
#define CIN 256
#define ADIM 128
#define MTOT (BATCH*NTOK)
#define NEG_SLOPE 0.2f

// ---------------- scratch ----------------
__device__ __nv_bfloat16 g_Xh[MTOT * CIN];
__device__ __nv_bfloat16 g_Xl[MTOT * CIN];
__device__ __nv_bfloat16 g_Qh[MTOT * ADIM];
__device__ __nv_bfloat16 g_Ql[MTOT * ADIM];
__device__ __nv_bfloat16 g_Kh[MTOT * ADIM];
__device__ __nv_bfloat16 g_Kl[MTOT * ADIM];
__device__ __nv_bfloat16 g_Vh[MTOT * ADIM];
__device__ __nv_bfloat16 g_Vl[MTOT * ADIM];
__device__ __nv_bfloat16 g_Oh[MTOT * ADIM];
__device__ __nv_bfloat16 g_Ol[MTOT * ADIM];
__device__ __nv_bfloat16 g_Wqh[CIN * ADIM], g_Wql[CIN * ADIM];
__device__ __nv_bfloat16 g_Wkh[CIN * ADIM], g_Wkl[CIN * ADIM];
__device__ __nv_bfloat16 g_Wvh[CIN * ADIM], g_Wvl[CIN * ADIM];
__device__ __nv_bfloat16 g_Woh[ADIM * CIN], g_Wol[ADIM * CIN];

__device__ __forceinline__ float lrelu(float x) { return x >= 0.0f ? x : NEG_SLOPE * x; }

// ---------------- helpers ----------------
__device__ __forceinline__ uint32_t smem_u32(const void* p) {
    uint32_t a;
    asm("{ .reg .u64 t; cvta.to.shared.u64 t, %1; cvt.u32.u64 %0, t; }" : "=r"(a) : "l"(p));
    return a;
}
__device__ __forceinline__ void cp16(uint32_t dst, const void* src) {
    asm volatile("cp.async.cg.shared.global [%0], [%1], 16;" :: "r"(dst), "l"(src));
}
__device__ __forceinline__ void cp_commit() { asm volatile("cp.async.commit_group;" ::: "memory"); }
__device__ __forceinline__ void cp_wait0() { asm volatile("cp.async.wait_group 0;" ::: "memory"); }
__device__ __forceinline__ void cp_wait1() { asm volatile("cp.async.wait_group 1;" ::: "memory"); }

__device__ __forceinline__ void ldsm4(uint32_t* r, uint32_t a) {
    asm volatile("ldmatrix.sync.aligned.m8n8.x4.shared.b16 {%0,%1,%2,%3}, [%4];"
        : "=r"(r[0]), "=r"(r[1]), "=r"(r[2]), "=r"(r[3]) : "r"(a));
}
__device__ __forceinline__ void ldsm4t(uint32_t* r, uint32_t a) {
    asm volatile("ldmatrix.sync.aligned.m8n8.x4.trans.shared.b16 {%0,%1,%2,%3}, [%4];"
        : "=r"(r[0]), "=r"(r[1]), "=r"(r[2]), "=r"(r[3]) : "r"(a));
}
__device__ __forceinline__ void mma_bf16(float* d, const uint32_t* a, const uint32_t* b) {
    asm volatile(
        "mma.sync.aligned.m16n8k16.row.col.f32.bf16.bf16.f32 "
        "{%0,%1,%2,%3}, {%4,%5,%6,%7}, {%8,%9}, {%0,%1,%2,%3};"
        : "+f"(d[0]), "+f"(d[1]), "+f"(d[2]), "+f"(d[3])
        : "r"(a[0]), "r"(a[1]), "r"(a[2]), "r"(a[3]), "r"(b[0]), "r"(b[1]));
}
__device__ __forceinline__ uint32_t bf2bits(__nv_bfloat162 v) { return *(uint32_t*)&v; }

__device__ __forceinline__ void split2(float f0, float f1, __nv_bfloat162& h, __nv_bfloat162& l) {
    h = __floats2bfloat162_rn(f0, f1);
    l = __floats2bfloat162_rn(f0 - __bfloat162float(h.x), f1 - __bfloat162float(h.y));
}

// =====================================================================
// Convert kernels: fp32 -> bf16 hi/lo
// =====================================================================
__global__ __launch_bounds__(256)
void convx_kernel(const float* __restrict__ X) {
    int i = blockIdx.x * 256 + threadIdx.x;
    float4 v = ((const float4*)X)[i];
    __nv_bfloat162 h0, l0, h1, l1;
    split2(v.x, v.y, h0, l0);
    split2(v.z, v.w, h1, l1);
    ((__nv_bfloat162*)g_Xh)[2 * i] = h0;
    ((__nv_bfloat162*)g_Xh)[2 * i + 1] = h1;
    ((__nv_bfloat162*)g_Xl)[2 * i] = l0;
    ((__nv_bfloat162*)g_Xl)[2 * i + 1] = l1;
}

__global__ __launch_bounds__(256)
void convw_kernel(const float* __restrict__ Wq, const float* __restrict__ Wk,
                  const float* __restrict__ Wv, const float* __restrict__ Wo) {
    int j = blockIdx.x * 256 + threadIdx.x;
    int sel = j >> 13;
    int loc = j & 8191;
    const float* src = (sel == 0) ? Wq : (sel == 1) ? Wk : (sel == 2) ? Wv : Wo;
    __nv_bfloat16* dh = (sel == 0) ? g_Wqh : (sel == 1) ? g_Wkh : (sel == 2) ? g_Wvh : g_Woh;
    __nv_bfloat16* dl = (sel == 0) ? g_Wql : (sel == 1) ? g_Wkl : (sel == 2) ? g_Wvl : g_Wol;
    float4 v = ((const float4*)src)[loc];
    __nv_bfloat162 h0, l0, h1, l1;
    split2(v.x, v.y, h0, l0);
    split2(v.z, v.w, h1, l1);
    ((__nv_bfloat162*)dh)[2 * loc] = h0;
    ((__nv_bfloat162*)dh)[2 * loc + 1] = h1;
    ((__nv_bfloat162*)dl)[2 * loc] = l0;
    ((__nv_bfloat162*)dl)[2 * loc + 1] = l1;
}

// =====================================================================
// Kernel 1: QKV projection via mma.sync, 3xBF16 split.
// grid (128, 3), 256 threads.
// =====================================================================
#define QKV2_XH 0
#define QKV2_XL 16384
#define QKV2_WH 32768
#define QKV2_WL 49152
#define QKV2_SMEM 65536

__global__ __launch_bounds__(256)
void qkv2_kernel() {
    extern __shared__ char smc[];
    const uint32_t sb = smem_u32(smc);
    const int tid = threadIdx.x;
    const int w = tid >> 5;
    const int lane = tid & 31;
    const int row0 = blockIdx.x * 128;

    const __nv_bfloat16 *WH, *WL;
    __nv_bfloat16 *OH, *OL;
    if (blockIdx.y == 0)      { WH = g_Wqh; WL = g_Wql; OH = g_Qh; OL = g_Ql; }
    else if (blockIdx.y == 1) { WH = g_Wkh; WL = g_Wkl; OH = g_Kh; OL = g_Kl; }
    else                      { WH = g_Wvh; WL = g_Wvl; OH = g_Vh; OL = g_Vl; }

    const int rowa = 16 * w + (lane & 15);
    const int ca = lane >> 4, swa = rowa & 7;
    const int rowv = (lane & 7) + (lane & 8);
    const int cv = (lane >> 4) & 1, swv = rowv & 7;

    float oacc[16][4];
    #pragma unroll
    for (int nb = 0; nb < 16; nb++)
        #pragma unroll
        for (int i = 0; i < 4; i++) oacc[nb][i] = 0.0f;

    #pragma unroll 1
    for (int kc = 0; kc < 4; kc++) {
        #pragma unroll
        for (int i = 0; i < 4; i++) {
            int lin = tid + i * 256;
            int r = lin >> 3, c = lin & 7;
            uint32_t off = (uint32_t)(r * 128 + ((c ^ (r & 7)) << 4));
            size_t g = (size_t)(row0 + r) * CIN + kc * 64 + c * 8;
            cp16(sb + QKV2_XH + off, g_Xh + g);
            cp16(sb + QKV2_XL + off, g_Xl + g);
        }
        #pragma unroll
        for (int i = 0; i < 4; i++) {
            int lin = tid + i * 256;
            int r = lin >> 4, c = lin & 15;
            uint32_t off = (uint32_t)(r * 256 + ((c ^ (r & 7)) << 4));
            size_t g = (size_t)(kc * 64 + r) * ADIM + c * 8;
            cp16(sb + QKV2_WH + off, WH + g);
            cp16(sb + QKV2_WL + off, WL + g);
        }
        cp_commit(); cp_wait0();
        __syncthreads();
        #pragma unroll
        for (int ks = 0; ks < 4; ks++) {
            uint32_t ah[4], al[4];
            uint32_t ach = (uint32_t)(((2 * ks + ca) ^ swa) << 4);
            ldsm4(ah, sb + QKV2_XH + rowa * 128 + ach);
            ldsm4(al, sb + QKV2_XL + rowa * 128 + ach);
            #pragma unroll
            for (int jp = 0; jp < 8; jp++) {
                uint32_t bh[4], bl[4];
                uint32_t boff = (uint32_t)((16 * ks + rowv) * 256 + (((2 * jp + cv) ^ swv) << 4));
                ldsm4t(bh, sb + QKV2_WH + boff);
                ldsm4t(bl, sb + QKV2_WL + boff);
                mma_bf16(oacc[2 * jp],     ah, bh); mma_bf16(oacc[2 * jp + 1], ah, bh + 2);
                mma_bf16(oacc[2 * jp],     ah, bl); mma_bf16(oacc[2 * jp + 1], ah, bl + 2);
                mma_bf16(oacc[2 * jp],     al, bh); mma_bf16(oacc[2 * jp + 1], al, bh + 2);
            }
        }
        __syncthreads();
    }

    const int r0 = row0 + 16 * w + (lane >> 2);
    const int cb2 = 2 * (lane & 3);
    #pragma unroll
    for (int nb = 0; nb < 16; nb++) {
        int c = nb * 8 + cb2;
        __nv_bfloat162 h01, l01, h23, l23;
        split2(lrelu(oacc[nb][0]), lrelu(oacc[nb][1]), h01, l01);
        split2(lrelu(oacc[nb][2]), lrelu(oacc[nb][3]), h23, l23);
        *(__nv_bfloat162*)&OH[(size_t)r0 * ADIM + c] = h01;
        *(__nv_bfloat162*)&OL[(size_t)r0 * ADIM + c] = l01;
        *(__nv_bfloat162*)&OH[(size_t)(r0 + 8) * ADIM + c] = h23;
        *(__nv_bfloat162*)&OL[(size_t)(r0 + 8) * ADIM + c] = l23;
    }
}

// =====================================================================
// Kernel 2: flash attention, mma.sync bf16 3-pass.
// grid (64, 4), 128 threads (4 warps), 2 CTAs/SM.
// CTA: 64 q rows; KV tiles of 32 rows, double buffered.
// smem: Qh 16K | Ql 16K | 2 x {Kh 8K | Kl 8K | Vh 8K | Vl 8K} = 96KB
// =====================================================================
#define SQH 0
#define SQL 16384
#define SKV 32768
#define ATTN_SMEM (32768 + 2*32768)

__device__ __forceinline__ void load_kv(uint32_t dst, const __nv_bfloat16* kh,
                                        const __nv_bfloat16* kl, const __nv_bfloat16* vh,
                                        const __nv_bfloat16* vl, int tid) {
    #pragma unroll
    for (int i = 0; i < 4; i++) {
        int lin = tid + i * 128;            // 512 chunks of 16B per sub-tile
        int r = lin >> 4, c = lin & 15;
        uint32_t off = (uint32_t)(r * 256 + ((c ^ (r & 7)) << 4));
        size_t g = (size_t)r * ADIM + c * 8;
        cp16(dst + off, kh + g);
        cp16(dst + 8192 + off, kl + g);
        cp16(dst + 16384 + off, vh + g);
        cp16(dst + 24576 + off, vl + g);
    }
}

__global__ __launch_bounds__(128, 2)
void attn_kernel() {
    extern __shared__ char smc[];
    const uint32_t sb = smem_u32(smc);
    const int tid = threadIdx.x;
    const int w = tid >> 5;
    const int lane = tid & 31;
    const int b = blockIdx.y;
    const int q0 = blockIdx.x * 64;

    // ---- load Q (hi+lo), 64 rows ----
    {
        const __nv_bfloat16* qh = g_Qh + (size_t)(b * NTOK + q0) * ADIM;
        const __nv_bfloat16* ql = g_Ql + (size_t)(b * NTOK + q0) * ADIM;
        #pragma unroll
        for (int i = 0; i < 8; i++) {
            int lin = tid + i * 128;        // 1024 chunks
            int r = lin >> 4, c = lin & 15;
            uint32_t off = (uint32_t)(r * 256 + ((c ^ (r & 7)) << 4));
            size_t g = (size_t)r * ADIM + c * 8;
            cp16(sb + SQH + off, qh + g);
            cp16(sb + SQL + off, ql + g);
        }
    }
    const __nv_bfloat16* KHb = g_Kh + (size_t)b * NTOK * ADIM;
    const __nv_bfloat16* KLb = g_Kl + (size_t)b * NTOK * ADIM;
    const __nv_bfloat16* VHb = g_Vh + (size_t)b * NTOK * ADIM;
    const __nv_bfloat16* VLb = g_Vl + (size_t)b * NTOK * ADIM;
    load_kv(sb + SKV, KHb, KLb, VHb, VLb, tid);
    cp_commit();

    const int rowa = 16 * w + (lane & 15);
    const uint32_t qro = (uint32_t)rowa * 256;
    const int ca = lane >> 4;
    const int swa = rowa & 7;
    const int rowb = (lane & 7) + ((lane & 16) >> 1);
    const int cb = (lane >> 3) & 1;
    const int swb = rowb & 7;
    const int rowv = (lane & 7) + (lane & 8);
    const int cv = (lane >> 4) & 1;
    const int swv = rowv & 7;

    float oacc[16][4];
    #pragma unroll
    for (int nb = 0; nb < 16; nb++)
        #pragma unroll
        for (int i = 0; i < 4; i++) oacc[nb][i] = 0.0f;
    float m0 = -CUDART_INF_F, m8 = -CUDART_INF_F, l0 = 0.0f, l8 = 0.0f;

    #pragma unroll 1
    for (int t = 0; t < 128; t++) {
        __syncthreads();
        if (t < 127) {
            uint32_t nb_ = sb + SKV + (uint32_t)((t + 1) & 1) * 32768u;
            size_t o = (size_t)(t + 1) * 32 * ADIM;
            load_kv(nb_, KHb + o, KLb + o, VHb + o, VLb + o, tid);
            cp_commit();
            cp_wait1();
        } else {
            cp_wait0();
        }
        __syncthreads();

        const uint32_t KB = sb + SKV + (uint32_t)(t & 1) * 32768u;
        const uint32_t VB = KB + 16384u;

        // ---- S = Qh*Kh^T + Qh*Kl^T + Ql*Kh^T  (16 rows x 32 cols per warp) ----
        float sacc[4][4];
        #pragma unroll
        for (int nb = 0; nb < 4; nb++)
            #pragma unroll
            for (int i = 0; i < 4; i++) sacc[nb][i] = 0.0f;

        #pragma unroll
        for (int ks = 0; ks < 8; ks++) {
            uint32_t aqh[4], aql[4];
            uint32_t ach = (uint32_t)(((2 * ks + ca) ^ swa) << 4);
            ldsm4(aqh, sb + SQH + qro + ach);
            ldsm4(aql, sb + SQL + qro + ach);
            uint32_t bch = (uint32_t)(((2 * ks + cb) ^ swb) << 4);
            #pragma unroll
            for (int jp = 0; jp < 2; jp++) {
                uint32_t bh[4], bl[4];
                uint32_t boff = (uint32_t)((16 * jp + rowb) * 256) + bch;
                ldsm4(bh, KB + boff);
                ldsm4(bl, KB + 8192u + boff);
                mma_bf16(sacc[2 * jp],     aqh, bh);
                mma_bf16(sacc[2 * jp + 1], aqh, bh + 2);
                mma_bf16(sacc[2 * jp],     aqh, bl);
                mma_bf16(sacc[2 * jp + 1], aqh, bl + 2);
                mma_bf16(sacc[2 * jp],     aql, bh);
                mma_bf16(sacc[2 * jp + 1], aql, bh + 2);
            }
        }

        // ---- online softmax (quad reduction over lanes sharing a row) ----
        float rm0 = sacc[0][0], rm8 = sacc[0][2];
        #pragma unroll
        for (int nb = 0; nb < 4; nb++) {
            rm0 = fmaxf(rm0, fmaxf(sacc[nb][0], sacc[nb][1]));
            rm8 = fmaxf(rm8, fmaxf(sacc[nb][2], sacc[nb][3]));
        }
        rm0 = fmaxf(rm0, __shfl_xor_sync(0xffffffffu, rm0, 1));
        rm0 = fmaxf(rm0, __shfl_xor_sync(0xffffffffu, rm0, 2));
        rm8 = fmaxf(rm8, __shfl_xor_sync(0xffffffffu, rm8, 1));
        rm8 = fmaxf(rm8, __shfl_xor_sync(0xffffffffu, rm8, 2));
        float mn0 = fmaxf(m0, rm0), mn8 = fmaxf(m8, rm8);
        float sc0 = __expf(m0 - mn0), sc8 = __expf(m8 - mn8);
        m0 = mn0; m8 = mn8;

        uint32_t ph[4][2], pl[4][2];
        float ls0 = 0.0f, ls8 = 0.0f;
        #pragma unroll
        for (int nb = 0; nb < 4; nb++) {
            float p0 = __expf(sacc[nb][0] - mn0);
            float p1 = __expf(sacc[nb][1] - mn0);
            float p2 = __expf(sacc[nb][2] - mn8);
            float p3 = __expf(sacc[nb][3] - mn8);
            ls0 += p0 + p1; ls8 += p2 + p3;
            __nv_bfloat162 h01, l01, h23, l23;
            split2(p0, p1, h01, l01);
            split2(p2, p3, h23, l23);
            ph[nb][0] = bf2bits(h01);
            ph[nb][1] = bf2bits(h23);
            pl[nb][0] = bf2bits(l01);
            pl[nb][1] = bf2bits(l23);
        }
        l0 = l0 * sc0 + ls0;
        l8 = l8 * sc8 + ls8;
        // rescale only when max actually moved (rare after warmup)
        if (sc0 < 1.0f) {
            #pragma unroll
            for (int nb = 0; nb < 16; nb++) { oacc[nb][0] *= sc0; oacc[nb][1] *= sc0; }
        }
        if (sc8 < 1.0f) {
            #pragma unroll
            for (int nb = 0; nb < 16; nb++) { oacc[nb][2] *= sc8; oacc[nb][3] *= sc8; }
        }

        // ---- O += Ph*Vh + Ph*Vl + Pl*Vh ----
        #pragma unroll
        for (int ks = 0; ks < 2; ks++) {
            uint32_t ah[4] = { ph[2 * ks][0], ph[2 * ks][1], ph[2 * ks + 1][0], ph[2 * ks + 1][1] };
            uint32_t al[4] = { pl[2 * ks][0], pl[2 * ks][1], pl[2 * ks + 1][0], pl[2 * ks + 1][1] };
            uint32_t vro = (uint32_t)((16 * ks + rowv) * 256);
            #pragma unroll
            for (int jp = 0; jp < 8; jp++) {
                uint32_t bh[4], bl[4];
                uint32_t voff = vro + (uint32_t)(((2 * jp + cv) ^ swv) << 4);
                ldsm4t(bh, VB + voff);
                ldsm4t(bl, VB + 8192u + voff);
                mma_bf16(oacc[2 * jp],     ah, bh);
                mma_bf16(oacc[2 * jp + 1], ah, bh + 2);
                mma_bf16(oacc[2 * jp],     ah, bl);
                mma_bf16(oacc[2 * jp + 1], ah, bl + 2);
                mma_bf16(oacc[2 * jp],     al, bh);
                mma_bf16(oacc[2 * jp + 1], al, bh + 2);
            }
        }
    }

    // ---- epilogue: normalize, split to bf16 hi/lo ----
    l0 += __shfl_xor_sync(0xffffffffu, l0, 1);
    l0 += __shfl_xor_sync(0xffffffffu, l0, 2);
    l8 += __shfl_xor_sync(0xffffffffu, l8, 1);
    l8 += __shfl_xor_sync(0xffffffffu, l8, 2);
    float inv0 = 1.0f / l0, inv8 = 1.0f / l8;
    size_t r0 = (size_t)b * NTOK + q0 + 16 * w + (lane >> 2);
    int cb2 = 2 * (lane & 3);
    #pragma unroll
    for (int nb = 0; nb < 16; nb++) {
        int c = nb * 8 + cb2;
        __nv_bfloat162 h01, l01, h23, l23;
        split2(oacc[nb][0] * inv0, oacc[nb][1] * inv0, h01, l01);
        split2(oacc[nb][2] * inv8, oacc[nb][3] * inv8, h23, l23);
        *(__nv_bfloat162*)&g_Oh[r0 * ADIM + c] = h01;
        *(__nv_bfloat162*)&g_Ol[r0 * ADIM + c] = l01;
        *(__nv_bfloat162*)&g_Oh[(r0 + 8) * ADIM + c] = h23;
        *(__nv_bfloat162*)&g_Ol[(r0 + 8) * ADIM + c] = l23;
    }
}

// =====================================================================
// Kernel 3: Y = O @ Wo * tanh(relu(1+wg)) via mma.sync, 3xBF16 split.
// grid (128, 2), 256 threads.
// =====================================================================
#define OUT2_AH 0
#define OUT2_AL 16384
#define OUT2_WH 32768
#define OUT2_WL 49152
#define OUT2_SMEM 65536

__global__ __launch_bounds__(256)
void out2_kernel(const float* __restrict__ wgm, float* __restrict__ Y) {
    extern __shared__ char smc[];
    const uint32_t sb = smem_u32(smc);
    const int tid = threadIdx.x;
    const int w = tid >> 5;
    const int lane = tid & 31;
    const int row0 = blockIdx.x * 128;
    const int col0 = blockIdx.y * 128;

    const int rowa = 16 * w + (lane & 15);
    const int ca = lane >> 4, swa = rowa & 7;
    const int rowv = (lane & 7) + (lane & 8);
    const int cv = (lane >> 4) & 1, swv = rowv & 7;

    float oacc[16][4];
    #pragma unroll
    for (int nb = 0; nb < 16; nb++)
        #pragma unroll
        for (int i = 0; i < 4; i++) oacc[nb][i] = 0.0f;

    #pragma unroll 1
    for (int kc = 0; kc < 2; kc++) {
        #pragma unroll
        for (int i = 0; i < 4; i++) {
            int lin = tid + i * 256;
            int r = lin >> 3, c = lin & 7;
            uint32_t off = (uint32_t)(r * 128 + ((c ^ (r & 7)) << 4));
            size_t g = (size_t)(row0 + r) * ADIM + kc * 64 + c * 8;
            cp16(sb + OUT2_AH + off, g_Oh + g);
            cp16(sb + OUT2_AL + off, g_Ol + g);
        }
        #pragma unroll
        for (int i = 0; i < 4; i++) {
            int lin = tid + i * 256;
            int r = lin >> 4, c = lin & 15;
            uint32_t off = (uint32_t)(r * 256 + ((c ^ (r & 7)) << 4));
            size_t g = (size_t)(kc * 64 + r) * CIN + col0 + c * 8;
            cp16(sb + OUT2_WH + off, g_Woh + g);
            cp16(sb + OUT2_WL + off, g_Wol + g);
        }
        cp_commit(); cp_wait0();
        __syncthreads();
        #pragma unroll
        for (int ks = 0; ks < 4; ks++) {
            uint32_t ah[4], al[4];
            uint32_t ach = (uint32_t)(((2 * ks + ca) ^ swa) << 4);
            ldsm4(ah, sb + OUT2_AH + rowa * 128 + ach);
            ldsm4(al, sb + OUT2_AL + rowa * 128 + ach);
            #pragma unroll
            for (int jp = 0; jp < 8; jp++) {
                uint32_t bh[4], bl[4];
                uint32_t boff = (uint32_t)((16 * ks + rowv) * 256 + (((2 * jp + cv) ^ swv) << 4));
                ldsm4t(bh, sb + OUT2_WH + boff);
                ldsm4t(bl, sb + OUT2_WL + boff);
                mma_bf16(oacc[2 * jp],     ah, bh); mma_bf16(oacc[2 * jp + 1], ah, bh + 2);
                mma_bf16(oacc[2 * jp],     ah, bl); mma_bf16(oacc[2 * jp + 1], ah, bl + 2);
                mma_bf16(oacc[2 * jp],     al, bh); mma_bf16(oacc[2 * jp + 1], al, bh + 2);
            }
        }
        __syncthreads();
    }

    const int r0 = row0 + 16 * w + (lane >> 2);
    const int cb2 = 2 * (lane & 3);
    #pragma unroll
    for (int nb = 0; nb < 16; nb++) {
        int c = col0 + nb * 8 + cb2;
        float g0 = tanhf(fmaxf(1.0f + wgm[c], 0.0f));
        float g1 = tanhf(fmaxf(1.0f + wgm[c + 1], 0.0f));
        *(float2*)&Y[(size_t)r0 * CIN + c] =
            make_float2(oacc[nb][0] * g0, oacc[nb][1] * g1);
        *(float2*)&Y[(size_t)(r0 + 8) * CIN + c] =
            make_float2(oacc[nb][2] * g0, oacc[nb][3] * g1);
    }
}

// =====================================================================
extern "C" void kernel_launch(void* const* d_in, const int* in_sizes, int n_in,
                              void* d_out, int out_size) {
    const float* x  = (const float*)d_in[0];
    const float* Wq = (const float*)d_in[1];
    const float* Wk = (const float*)d_in[2];
    const float* Wv = (const float*)d_in[3];
    const float* Wo = (const float*)d_in[4];
    const float* wg = (const float*)d_in[5];
    float* y = (float*)d_out;

    static bool attrs_set = []() {
        cudaFuncSetAttribute(qkv2_kernel, cudaFuncAttributeMaxDynamicSharedMemorySize, QKV2_SMEM);
        cudaFuncSetAttribute(attn_kernel, cudaFuncAttributeMaxDynamicSharedMemorySize, ATTN_SMEM);
        cudaFuncSetAttribute(out2_kernel, cudaFuncAttributeMaxDynamicSharedMemorySize, OUT2_SMEM);
        return true;
    }();
    (void)attrs_set;

    convx_kernel<<<4096, 256>>>(x);
    convw_kernel<<<128, 256>>>(Wq, Wk, Wv, Wo);
    qkv2_kernel<<<dim3(128, 3), 256, QKV2_SMEM>>>();
    attn_kernel<<<dim3(NTOK / 64, BATCH), 128, ATTN_SMEM>>>();
    out2_kernel<<<dim3(128, 2), 256, OUT2_SMEM>>>(wg, y);
}

// round 7
// speedup vs baseline: 1.0179x; 1.0179x over previous
#include <cuda_runtime.h>
#include <cuda_bf16.h>
#include <math_constants.h>
#include <stdint.h>

#define BATCH 4
#define NTOK 4096
#define CIN 256
#define ADIM 128
#define MTOT (BATCH*NTOK)
#define NEG_SLOPE 0.2f

// ---------------- scratch ----------------
__device__ __nv_bfloat16 g_Xh[MTOT * CIN];
__device__ __nv_bfloat16 g_Xl[MTOT * CIN];
__device__ __nv_bfloat16 g_Qh[MTOT * ADIM];
__device__ __nv_bfloat16 g_Ql[MTOT * ADIM];
__device__ __nv_bfloat16 g_Kh[MTOT * ADIM];
__device__ __nv_bfloat16 g_Kl[MTOT * ADIM];
__device__ __nv_bfloat16 g_Vh[MTOT * ADIM];
__device__ __nv_bfloat16 g_Vl[MTOT * ADIM];
__device__ __nv_bfloat16 g_Oh[MTOT * ADIM];
__device__ __nv_bfloat16 g_Ol[MTOT * ADIM];
__device__ __nv_bfloat16 g_Wqh[CIN * ADIM], g_Wql[CIN * ADIM];
__device__ __nv_bfloat16 g_Wkh[CIN * ADIM], g_Wkl[CIN * ADIM];
__device__ __nv_bfloat16 g_Wvh[CIN * ADIM], g_Wvl[CIN * ADIM];
__device__ __nv_bfloat16 g_Woh[ADIM * CIN], g_Wol[ADIM * CIN];

__device__ __forceinline__ float lrelu(float x) { return x >= 0.0f ? x : NEG_SLOPE * x; }

// ---------------- helpers ----------------
__device__ __forceinline__ uint32_t smem_u32(const void* p) {
    uint32_t a;
    asm("{ .reg .u64 t; cvta.to.shared.u64 t, %1; cvt.u32.u64 %0, t; }" : "=r"(a) : "l"(p));
    return a;
}
__device__ __forceinline__ void cp16(uint32_t dst, const void* src) {
    asm volatile("cp.async.cg.shared.global [%0], [%1], 16;" :: "r"(dst), "l"(src));
}
__device__ __forceinline__ void cp_commit() { asm volatile("cp.async.commit_group;" ::: "memory"); }
__device__ __forceinline__ void cp_wait0() { asm volatile("cp.async.wait_group 0;" ::: "memory"); }

__device__ __forceinline__ void ldsm4(uint32_t* r, uint32_t a) {
    asm volatile("ldmatrix.sync.aligned.m8n8.x4.shared.b16 {%0,%1,%2,%3}, [%4];"
        : "=r"(r[0]), "=r"(r[1]), "=r"(r[2]), "=r"(r[3]) : "r"(a));
}
__device__ __forceinline__ void ldsm4t(uint32_t* r, uint32_t a) {
    asm volatile("ldmatrix.sync.aligned.m8n8.x4.trans.shared.b16 {%0,%1,%2,%3}, [%4];"
        : "=r"(r[0]), "=r"(r[1]), "=r"(r[2]), "=r"(r[3]) : "r"(a));
}
__device__ __forceinline__ void mma_bf16(float* d, const uint32_t* a, const uint32_t* b) {
    asm volatile(
        "mma.sync.aligned.m16n8k16.row.col.f32.bf16.bf16.f32 "
        "{%0,%1,%2,%3}, {%4,%5,%6,%7}, {%8,%9}, {%0,%1,%2,%3};"
        : "+f"(d[0]), "+f"(d[1]), "+f"(d[2]), "+f"(d[3])
        : "r"(a[0]), "r"(a[1]), "r"(a[2]), "r"(a[3]), "r"(b[0]), "r"(b[1]));
}
__device__ __forceinline__ uint32_t bf2bits(__nv_bfloat162 v) { return *(uint32_t*)&v; }

__device__ __forceinline__ void split2(float f0, float f1, __nv_bfloat162& h, __nv_bfloat162& l) {
    h = __floats2bfloat162_rn(f0, f1);
    l = __floats2bfloat162_rn(f0 - __bfloat162float(h.x), f1 - __bfloat162float(h.y));
}

// =====================================================================
// Convert kernels: fp32 -> bf16 hi/lo
// =====================================================================
__global__ __launch_bounds__(256)
void convx_kernel(const float* __restrict__ X) {
    int i = blockIdx.x * 256 + threadIdx.x;
    float4 v = ((const float4*)X)[i];
    __nv_bfloat162 h0, l0, h1, l1;
    split2(v.x, v.y, h0, l0);
    split2(v.z, v.w, h1, l1);
    ((__nv_bfloat162*)g_Xh)[2 * i] = h0;
    ((__nv_bfloat162*)g_Xh)[2 * i + 1] = h1;
    ((__nv_bfloat162*)g_Xl)[2 * i] = l0;
    ((__nv_bfloat162*)g_Xl)[2 * i + 1] = l1;
}

__global__ __launch_bounds__(256)
void convw_kernel(const float* __restrict__ Wq, const float* __restrict__ Wk,
                  const float* __restrict__ Wv, const float* __restrict__ Wo) {
    int j = blockIdx.x * 256 + threadIdx.x;
    int sel = j >> 13;
    int loc = j & 8191;
    const float* src = (sel == 0) ? Wq : (sel == 1) ? Wk : (sel == 2) ? Wv : Wo;
    __nv_bfloat16* dh = (sel == 0) ? g_Wqh : (sel == 1) ? g_Wkh : (sel == 2) ? g_Wvh : g_Woh;
    __nv_bfloat16* dl = (sel == 0) ? g_Wql : (sel == 1) ? g_Wkl : (sel == 2) ? g_Wvl : g_Wol;
    float4 v = ((const float4*)src)[loc];
    __nv_bfloat162 h0, l0, h1, l1;
    split2(v.x, v.y, h0, l0);
    split2(v.z, v.w, h1, l1);
    ((__nv_bfloat162*)dh)[2 * loc] = h0;
    ((__nv_bfloat162*)dh)[2 * loc + 1] = h1;
    ((__nv_bfloat162*)dl)[2 * loc] = l0;
    ((__nv_bfloat162*)dl)[2 * loc + 1] = l1;
}

// =====================================================================
// Kernel 1: QKV projection via mma.sync, 3xBF16 split.
// grid (128, 3), 256 threads.
// =====================================================================
#define QKV2_XH 0
#define QKV2_XL 16384
#define QKV2_WH 32768
#define QKV2_WL 49152
#define QKV2_SMEM 65536

__global__ __launch_bounds__(256)
void qkv2_kernel() {
    extern __shared__ char smc[];
    const uint32_t sb = smem_u32(smc);
    const int tid = threadIdx.x;
    const int w = tid >> 5;
    const int lane = tid & 31;
    const int row0 = blockIdx.x * 128;

    const __nv_bfloat16 *WH, *WL;
    __nv_bfloat16 *OH, *OL;
    if (blockIdx.y == 0)      { WH = g_Wqh; WL = g_Wql; OH = g_Qh; OL = g_Ql; }
    else if (blockIdx.y == 1) { WH = g_Wkh; WL = g_Wkl; OH = g_Kh; OL = g_Kl; }
    else                      { WH = g_Wvh; WL = g_Wvl; OH = g_Vh; OL = g_Vl; }

    const int rowa = 16 * w + (lane & 15);
    const int ca = lane >> 4, swa = rowa & 7;
    const int rowv = (lane & 7) + (lane & 8);
    const int cv = (lane >> 4) & 1, swv = rowv & 7;

    float oacc[16][4];
    #pragma unroll
    for (int nb = 0; nb < 16; nb++)
        #pragma unroll
        for (int i = 0; i < 4; i++) oacc[nb][i] = 0.0f;

    #pragma unroll 1
    for (int kc = 0; kc < 4; kc++) {
        #pragma unroll
        for (int i = 0; i < 4; i++) {
            int lin = tid + i * 256;
            int r = lin >> 3, c = lin & 7;
            uint32_t off = (uint32_t)(r * 128 + ((c ^ (r & 7)) << 4));
            size_t g = (size_t)(row0 + r) * CIN + kc * 64 + c * 8;
            cp16(sb + QKV2_XH + off, g_Xh + g);
            cp16(sb + QKV2_XL + off, g_Xl + g);
        }
        #pragma unroll
        for (int i = 0; i < 4; i++) {
            int lin = tid + i * 256;
            int r = lin >> 4, c = lin & 15;
            uint32_t off = (uint32_t)(r * 256 + ((c ^ (r & 7)) << 4));
            size_t g = (size_t)(kc * 64 + r) * ADIM + c * 8;
            cp16(sb + QKV2_WH + off, WH + g);
            cp16(sb + QKV2_WL + off, WL + g);
        }
        cp_commit(); cp_wait0();
        __syncthreads();
        #pragma unroll
        for (int ks = 0; ks < 4; ks++) {
            uint32_t ah[4], al[4];
            uint32_t ach = (uint32_t)(((2 * ks + ca) ^ swa) << 4);
            ldsm4(ah, sb + QKV2_XH + rowa * 128 + ach);
            ldsm4(al, sb + QKV2_XL + rowa * 128 + ach);
            #pragma unroll
            for (int jp = 0; jp < 8; jp++) {
                uint32_t bh[4], bl[4];
                uint32_t boff = (uint32_t)((16 * ks + rowv) * 256 + (((2 * jp + cv) ^ swv) << 4));
                ldsm4t(bh, sb + QKV2_WH + boff);
                ldsm4t(bl, sb + QKV2_WL + boff);
                mma_bf16(oacc[2 * jp],     ah, bh); mma_bf16(oacc[2 * jp + 1], ah, bh + 2);
                mma_bf16(oacc[2 * jp],     ah, bl); mma_bf16(oacc[2 * jp + 1], ah, bl + 2);
                mma_bf16(oacc[2 * jp],     al, bh); mma_bf16(oacc[2 * jp + 1], al, bh + 2);
            }
        }
        __syncthreads();
    }

    const int r0 = row0 + 16 * w + (lane >> 2);
    const int cb2 = 2 * (lane & 3);
    #pragma unroll
    for (int nb = 0; nb < 16; nb++) {
        int c = nb * 8 + cb2;
        __nv_bfloat162 h01, l01, h23, l23;
        split2(lrelu(oacc[nb][0]), lrelu(oacc[nb][1]), h01, l01);
        split2(lrelu(oacc[nb][2]), lrelu(oacc[nb][3]), h23, l23);
        *(__nv_bfloat162*)&OH[(size_t)r0 * ADIM + c] = h01;
        *(__nv_bfloat162*)&OL[(size_t)r0 * ADIM + c] = l01;
        *(__nv_bfloat162*)&OH[(size_t)(r0 + 8) * ADIM + c] = h23;
        *(__nv_bfloat162*)&OL[(size_t)(r0 + 8) * ADIM + c] = l23;
    }
}

// =====================================================================
// Kernel 2: flash attention, mma.sync bf16 3-pass.
// grid (64, 4), 128 threads (4 warps), 2 CTAs/SM.
// CTA: 64 q rows; KV tile 64 rows, SINGLE buffer (co-resident CTA hides loads).
// smem: Qh 16K | Ql 16K | Kh 16K | Kl 16K | Vh 16K | Vl 16K = 96KB
// Per-CTA KV start-offset rotation decorrelates the two CTAs' phases.
// =====================================================================
#define SQH 0
#define SQL 16384
#define SKH 32768
#define SKL 49152
#define SVH 65536
#define SVL 81920
#define ATTN_SMEM 98304

__global__ __launch_bounds__(128, 2)
void attn_kernel() {
    extern __shared__ char smc[];
    const uint32_t sb = smem_u32(smc);
    const int tid = threadIdx.x;
    const int w = tid >> 5;
    const int lane = tid & 31;
    const int b = blockIdx.y;
    const int q0 = blockIdx.x * 64;
    const int tstart = (blockIdx.x & 1) * 32;   // phase rotation between paired CTAs

    // ---- load Q (hi+lo), 64 rows ----
    {
        const __nv_bfloat16* qh = g_Qh + (size_t)(b * NTOK + q0) * ADIM;
        const __nv_bfloat16* ql = g_Ql + (size_t)(b * NTOK + q0) * ADIM;
        #pragma unroll
        for (int i = 0; i < 8; i++) {
            int lin = tid + i * 128;        // 1024 chunks
            int r = lin >> 4, c = lin & 15;
            uint32_t off = (uint32_t)(r * 256 + ((c ^ (r & 7)) << 4));
            size_t g = (size_t)r * ADIM + c * 8;
            cp16(sb + SQH + off, qh + g);
            cp16(sb + SQL + off, ql + g);
        }
    }
    const __nv_bfloat16* KHb = g_Kh + (size_t)b * NTOK * ADIM;
    const __nv_bfloat16* KLb = g_Kl + (size_t)b * NTOK * ADIM;
    const __nv_bfloat16* VHb = g_Vh + (size_t)b * NTOK * ADIM;
    const __nv_bfloat16* VLb = g_Vl + (size_t)b * NTOK * ADIM;

    const int rowa = 16 * w + (lane & 15);
    const uint32_t qro = (uint32_t)rowa * 256;
    const int ca = lane >> 4;
    const int swa = rowa & 7;
    const int rowb = (lane & 7) + ((lane & 16) >> 1);
    const int cb = (lane >> 3) & 1;
    const int swb = rowb & 7;
    const int rowv = (lane & 7) + (lane & 8);
    const int cv = (lane >> 4) & 1;
    const int swv = rowv & 7;

    float oacc[16][4];
    #pragma unroll
    for (int nb = 0; nb < 16; nb++)
        #pragma unroll
        for (int i = 0; i < 4; i++) oacc[nb][i] = 0.0f;
    float m0 = -CUDART_INF_F, m8 = -CUDART_INF_F, l0 = 0.0f, l8 = 0.0f;

    #pragma unroll 1
    for (int t = 0; t < 64; t++) {
        const int tt = (t + tstart) & 63;
        __syncthreads();   // all warps done reading KV before overwrite
        {
            size_t o = (size_t)tt * 64 * ADIM;
            #pragma unroll
            for (int i = 0; i < 8; i++) {
                int lin = tid + i * 128;    // 1024 chunks per sub-tile
                int r = lin >> 4, c = lin & 15;
                uint32_t off = (uint32_t)(r * 256 + ((c ^ (r & 7)) << 4));
                size_t g = o + (size_t)r * ADIM + c * 8;
                cp16(sb + SKH + off, KHb + g);
                cp16(sb + SKL + off, KLb + g);
                cp16(sb + SVH + off, VHb + g);
                cp16(sb + SVL + off, VLb + g);
            }
        }
        cp_commit(); cp_wait0();
        __syncthreads();

        // ---- S = Qh*Kh^T + Qh*Kl^T + Ql*Kh^T  (16 rows x 64 cols per warp) ----
        float sacc[8][4];
        #pragma unroll
        for (int nb = 0; nb < 8; nb++)
            #pragma unroll
            for (int i = 0; i < 4; i++) sacc[nb][i] = 0.0f;

        #pragma unroll
        for (int ks = 0; ks < 8; ks++) {
            uint32_t aqh[4], aql[4];
            uint32_t ach = (uint32_t)(((2 * ks + ca) ^ swa) << 4);
            ldsm4(aqh, sb + SQH + qro + ach);
            ldsm4(aql, sb + SQL + qro + ach);
            uint32_t bch = (uint32_t)(((2 * ks + cb) ^ swb) << 4);
            #pragma unroll
            for (int jp = 0; jp < 4; jp++) {
                uint32_t bh[4], bl[4];
                uint32_t boff = (uint32_t)((16 * jp + rowb) * 256) + bch;
                ldsm4(bh, sb + SKH + boff);
                ldsm4(bl, sb + SKL + boff);
                mma_bf16(sacc[2 * jp],     aqh, bh);
                mma_bf16(sacc[2 * jp + 1], aqh, bh + 2);
                mma_bf16(sacc[2 * jp],     aqh, bl);
                mma_bf16(sacc[2 * jp + 1], aqh, bl + 2);
                mma_bf16(sacc[2 * jp],     aql, bh);
                mma_bf16(sacc[2 * jp + 1], aql, bh + 2);
            }
        }

        // ---- online softmax ----
        float rm0 = sacc[0][0], rm8 = sacc[0][2];
        #pragma unroll
        for (int nb = 0; nb < 8; nb++) {
            rm0 = fmaxf(rm0, fmaxf(sacc[nb][0], sacc[nb][1]));
            rm8 = fmaxf(rm8, fmaxf(sacc[nb][2], sacc[nb][3]));
        }
        rm0 = fmaxf(rm0, __shfl_xor_sync(0xffffffffu, rm0, 1));
        rm0 = fmaxf(rm0, __shfl_xor_sync(0xffffffffu, rm0, 2));
        rm8 = fmaxf(rm8, __shfl_xor_sync(0xffffffffu, rm8, 1));
        rm8 = fmaxf(rm8, __shfl_xor_sync(0xffffffffu, rm8, 2));
        float mn0 = fmaxf(m0, rm0), mn8 = fmaxf(m8, rm8);
        float sc0 = __expf(m0 - mn0), sc8 = __expf(m8 - mn8);
        m0 = mn0; m8 = mn8;

        uint32_t ph[8][2], pl[8][2];
        float ls0 = 0.0f, ls8 = 0.0f;
        #pragma unroll
        for (int nb = 0; nb < 8; nb++) {
            float p0 = __expf(sacc[nb][0] - mn0);
            float p1 = __expf(sacc[nb][1] - mn0);
            float p2 = __expf(sacc[nb][2] - mn8);
            float p3 = __expf(sacc[nb][3] - mn8);
            ls0 += p0 + p1; ls8 += p2 + p3;
            __nv_bfloat162 h01, l01, h23, l23;
            split2(p0, p1, h01, l01);
            split2(p2, p3, h23, l23);
            ph[nb][0] = bf2bits(h01);
            ph[nb][1] = bf2bits(h23);
            pl[nb][0] = bf2bits(l01);
            pl[nb][1] = bf2bits(l23);
        }
        l0 = l0 * sc0 + ls0;
        l8 = l8 * sc8 + ls8;
        if (sc0 < 1.0f) {
            #pragma unroll
            for (int nb = 0; nb < 16; nb++) { oacc[nb][0] *= sc0; oacc[nb][1] *= sc0; }
        }
        if (sc8 < 1.0f) {
            #pragma unroll
            for (int nb = 0; nb < 16; nb++) { oacc[nb][2] *= sc8; oacc[nb][3] *= sc8; }
        }

        // ---- O += Ph*Vh + Ph*Vl + Pl*Vh ----
        #pragma unroll
        for (int ks = 0; ks < 4; ks++) {
            uint32_t ah[4] = { ph[2 * ks][0], ph[2 * ks][1], ph[2 * ks + 1][0], ph[2 * ks + 1][1] };
            uint32_t al[4] = { pl[2 * ks][0], pl[2 * ks][1], pl[2 * ks + 1][0], pl[2 * ks + 1][1] };
            uint32_t vro = (uint32_t)((16 * ks + rowv) * 256);
            #pragma unroll
            for (int jp = 0; jp < 8; jp++) {
                uint32_t bh[4], bl[4];
                uint32_t voff = vro + (uint32_t)(((2 * jp + cv) ^ swv) << 4);
                ldsm4t(bh, sb + SVH + voff);
                ldsm4t(bl, sb + SVL + voff);
                mma_bf16(oacc[2 * jp],     ah, bh);
                mma_bf16(oacc[2 * jp + 1], ah, bh + 2);
                mma_bf16(oacc[2 * jp],     ah, bl);
                mma_bf16(oacc[2 * jp + 1], ah, bl + 2);
                mma_bf16(oacc[2 * jp],     al, bh);
                mma_bf16(oacc[2 * jp + 1], al, bh + 2);
            }
        }
    }

    // ---- epilogue: normalize, split to bf16 hi/lo ----
    l0 += __shfl_xor_sync(0xffffffffu, l0, 1);
    l0 += __shfl_xor_sync(0xffffffffu, l0, 2);
    l8 += __shfl_xor_sync(0xffffffffu, l8, 1);
    l8 += __shfl_xor_sync(0xffffffffu, l8, 2);
    float inv0 = 1.0f / l0, inv8 = 1.0f / l8;
    size_t r0 = (size_t)b * NTOK + q0 + 16 * w + (lane >> 2);
    int cb2 = 2 * (lane & 3);
    #pragma unroll
    for (int nb = 0; nb < 16; nb++) {
        int c = nb * 8 + cb2;
        __nv_bfloat162 h01, l01, h23, l23;
        split2(oacc[nb][0] * inv0, oacc[nb][1] * inv0, h01, l01);
        split2(oacc[nb][2] * inv8, oacc[nb][3] * inv8, h23, l23);
        *(__nv_bfloat162*)&g_Oh[r0 * ADIM + c] = h01;
        *(__nv_bfloat162*)&g_Ol[r0 * ADIM + c] = l01;
        *(__nv_bfloat162*)&g_Oh[(r0 + 8) * ADIM + c] = h23;
        *(__nv_bfloat162*)&g_Ol[(r0 + 8) * ADIM + c] = l23;
    }
}

// =====================================================================
// Kernel 3: Y = O @ Wo * tanh(relu(1+wg)) via mma.sync, 3xBF16 split.
// grid (128, 2), 256 threads.
// =====================================================================
#define OUT2_AH 0
#define OUT2_AL 16384
#define OUT2_WH 32768
#define OUT2_WL 49152
#define OUT2_SMEM 65536

__global__ __launch_bounds__(256)
void out2_kernel(const float* __restrict__ wgm, float* __restrict__ Y) {
    extern __shared__ char smc[];
    const uint32_t sb = smem_u32(smc);
    const int tid = threadIdx.x;
    const int w = tid >> 5;
    const int lane = tid & 31;
    const int row0 = blockIdx.x * 128;
    const int col0 = blockIdx.y * 128;

    const int rowa = 16 * w + (lane & 15);
    const int ca = lane >> 4, swa = rowa & 7;
    const int rowv = (lane & 7) + (lane & 8);
    const int cv = (lane >> 4) & 1, swv = rowv & 7;

    float oacc[16][4];
    #pragma unroll
    for (int nb = 0; nb < 16; nb++)
        #pragma unroll
        for (int i = 0; i < 4; i++) oacc[nb][i] = 0.0f;

    #pragma unroll 1
    for (int kc = 0; kc < 2; kc++) {
        #pragma unroll
        for (int i = 0; i < 4; i++) {
            int lin = tid + i * 256;
            int r = lin >> 3, c = lin & 7;
            uint32_t off = (uint32_t)(r * 128 + ((c ^ (r & 7)) << 4));
            size_t g = (size_t)(row0 + r) * ADIM + kc * 64 + c * 8;
            cp16(sb + OUT2_AH + off, g_Oh + g);
            cp16(sb + OUT2_AL + off, g_Ol + g);
        }
        #pragma unroll
        for (int i = 0; i < 4; i++) {
            int lin = tid + i * 256;
            int r = lin >> 4, c = lin & 15;
            uint32_t off = (uint32_t)(r * 256 + ((c ^ (r & 7)) << 4));
            size_t g = (size_t)(kc * 64 + r) * CIN + col0 + c * 8;
            cp16(sb + OUT2_WH + off, g_Woh + g);
            cp16(sb + OUT2_WL + off, g_Wol + g);
        }
        cp_commit(); cp_wait0();
        __syncthreads();
        #pragma unroll
        for (int ks = 0; ks < 4; ks++) {
            uint32_t ah[4], al[4];
            uint32_t ach = (uint32_t)(((2 * ks + ca) ^ swa) << 4);
            ldsm4(ah, sb + OUT2_AH + rowa * 128 + ach);
            ldsm4(al, sb + OUT2_AL + rowa * 128 + ach);
            #pragma unroll
            for (int jp = 0; jp < 8; jp++) {
                uint32_t bh[4], bl[4];
                uint32_t boff = (uint32_t)((16 * ks + rowv) * 256 + (((2 * jp + cv) ^ swv) << 4));
                ldsm4t(bh, sb + OUT2_WH + boff);
                ldsm4t(bl, sb + OUT2_WL + boff);
                mma_bf16(oacc[2 * jp],     ah, bh); mma_bf16(oacc[2 * jp + 1], ah, bh + 2);
                mma_bf16(oacc[2 * jp],     ah, bl); mma_bf16(oacc[2 * jp + 1], ah, bl + 2);
                mma_bf16(oacc[2 * jp],     al, bh); mma_bf16(oacc[2 * jp + 1], al, bh + 2);
            }
        }
        __syncthreads();
    }

    const int r0 = row0 + 16 * w + (lane >> 2);
    const int cb2 = 2 * (lane & 3);
    #pragma unroll
    for (int nb = 0; nb < 16; nb++) {
        int c = col0 + nb * 8 + cb2;
        float g0 = tanhf(fmaxf(1.0f + wgm[c], 0.0f));
        float g1 = tanhf(fmaxf(1.0f + wgm[c + 1], 0.0f));
        *(float2*)&Y[(size_t)r0 * CIN + c] =
            make_float2(oacc[nb][0] * g0, oacc[nb][1] * g1);
        *(float2*)&Y[(size_t)(r0 + 8) * CIN + c] =
            make_float2(oacc[nb][2] * g0, oacc[nb][3] * g1);
    }
}

// =====================================================================
extern "C" void kernel_launch(void* const* d_in, const int* in_sizes, int n_in,
                              void* d_out, int out_size) {
    const float* x  = (const float*)d_in[0];
    const float* Wq = (const float*)d_in[1];
    const float* Wk = (const float*)d_in[2];
    const float* Wv = (const float*)d_in[3];
    const float* Wo = (const float*)d_in[4];
    const float* wg = (const float*)d_in[5];
    float* y = (float*)d_out;

    static bool attrs_set = []() {
        cudaFuncSetAttribute(qkv2_kernel, cudaFuncAttributeMaxDynamicSharedMemorySize, QKV2_SMEM);
        cudaFuncSetAttribute(attn_kernel, cudaFuncAttributeMaxDynamicSharedMemorySize, ATTN_SMEM);
        cudaFuncSetAttribute(out2_kernel, cudaFuncAttributeMaxDynamicSharedMemorySize, OUT2_SMEM);
        return true;
    }();
    (void)attrs_set;

    convx_kernel<<<4096, 256>>>(x);
    convw_kernel<<<128, 256>>>(Wq, Wk, Wv, Wo);
    qkv2_kernel<<<dim3(128, 3), 256, QKV2_SMEM>>>();
    attn_kernel<<<dim3(NTOK / 64, BATCH), 128, ATTN_SMEM>>>();
    out2_kernel<<<dim3(128, 2), 256, OUT2_SMEM>>>(wg, y);
}

// round 8
// speedup vs baseline: 1.1506x; 1.1304x over previous
#include <cuda_runtime.h>
#include <cuda_bf16.h>
#include <cuda_fp16.h>
#include <math_constants.h>
#include <stdint.h>

#define BATCH 4
#define NTOK 4096
#define CIN 256
#define ADIM 128
#define MTOT (BATCH*NTOK)
#define NEG_SLOPE 0.2f
#define LOG2E 1.4426950408889634f

// ---------------- scratch ----------------
__device__ __nv_bfloat16 g_Xh[MTOT * CIN];
__device__ __nv_bfloat16 g_Xl[MTOT * CIN];
__device__ __nv_bfloat16 g_Qh[MTOT * ADIM];   // pre-scaled by log2(e)
__device__ __nv_bfloat16 g_Ql[MTOT * ADIM];
__device__ __nv_bfloat16 g_Kh[MTOT * ADIM];
__device__ __nv_bfloat16 g_Kl[MTOT * ADIM];
__device__ __half        g_Vh[MTOT * ADIM];   // fp16 split
__device__ __half        g_Vl[MTOT * ADIM];
__device__ __nv_bfloat16 g_Oh[MTOT * ADIM];
__device__ __nv_bfloat16 g_Ol[MTOT * ADIM];
__device__ __nv_bfloat16 g_Wqh[CIN * ADIM], g_Wql[CIN * ADIM];
__device__ __nv_bfloat16 g_Wkh[CIN * ADIM], g_Wkl[CIN * ADIM];
__device__ __nv_bfloat16 g_Wvh[CIN * ADIM], g_Wvl[CIN * ADIM];
__device__ __nv_bfloat16 g_Woh[ADIM * CIN], g_Wol[ADIM * CIN];

__device__ __forceinline__ float lrelu(float x) { return x >= 0.0f ? x : NEG_SLOPE * x; }

// ---------------- helpers ----------------
__device__ __forceinline__ uint32_t smem_u32(const void* p) {
    uint32_t a;
    asm("{ .reg .u64 t; cvta.to.shared.u64 t, %1; cvt.u32.u64 %0, t; }" : "=r"(a) : "l"(p));
    return a;
}
__device__ __forceinline__ void cp16(uint32_t dst, const void* src) {
    asm volatile("cp.async.cg.shared.global [%0], [%1], 16;" :: "r"(dst), "l"(src));
}
__device__ __forceinline__ void cp_commit() { asm volatile("cp.async.commit_group;" ::: "memory"); }
__device__ __forceinline__ void cp_wait0() { asm volatile("cp.async.wait_group 0;" ::: "memory"); }
__device__ __forceinline__ void cp_wait1() { asm volatile("cp.async.wait_group 1;" ::: "memory"); }

__device__ __forceinline__ void ldsm4(uint32_t* r, uint32_t a) {
    asm volatile("ldmatrix.sync.aligned.m8n8.x4.shared.b16 {%0,%1,%2,%3}, [%4];"
        : "=r"(r[0]), "=r"(r[1]), "=r"(r[2]), "=r"(r[3]) : "r"(a));
}
__device__ __forceinline__ void ldsm4t(uint32_t* r, uint32_t a) {
    asm volatile("ldmatrix.sync.aligned.m8n8.x4.trans.shared.b16 {%0,%1,%2,%3}, [%4];"
        : "=r"(r[0]), "=r"(r[1]), "=r"(r[2]), "=r"(r[3]) : "r"(a));
}
__device__ __forceinline__ void mma_bf16(float* d, const uint32_t* a, const uint32_t* b) {
    asm volatile(
        "mma.sync.aligned.m16n8k16.row.col.f32.bf16.bf16.f32 "
        "{%0,%1,%2,%3}, {%4,%5,%6,%7}, {%8,%9}, {%0,%1,%2,%3};"
        : "+f"(d[0]), "+f"(d[1]), "+f"(d[2]), "+f"(d[3])
        : "r"(a[0]), "r"(a[1]), "r"(a[2]), "r"(a[3]), "r"(b[0]), "r"(b[1]));
}
__device__ __forceinline__ void mma_f16(float* d, const uint32_t* a, const uint32_t* b) {
    asm volatile(
        "mma.sync.aligned.m16n8k16.row.col.f32.f16.f16.f32 "
        "{%0,%1,%2,%3}, {%4,%5,%6,%7}, {%8,%9}, {%0,%1,%2,%3};"
        : "+f"(d[0]), "+f"(d[1]), "+f"(d[2]), "+f"(d[3])
        : "r"(a[0]), "r"(a[1]), "r"(a[2]), "r"(a[3]), "r"(b[0]), "r"(b[1]));
}
__device__ __forceinline__ uint32_t bf2bits(__nv_bfloat162 v) { return *(uint32_t*)&v; }
__device__ __forceinline__ uint32_t h2bits(__half2 v) { return *(uint32_t*)&v; }
__device__ __forceinline__ float ex2(float x) {
    float r; asm("ex2.approx.f32 %0, %1;" : "=f"(r) : "f"(x)); return r;
}

__device__ __forceinline__ void split2(float f0, float f1, __nv_bfloat162& h, __nv_bfloat162& l) {
    h = __floats2bfloat162_rn(f0, f1);
    l = __floats2bfloat162_rn(f0 - __bfloat162float(h.x), f1 - __bfloat162float(h.y));
}
__device__ __forceinline__ void split2h(float f0, float f1, __half2& h, __half2& l) {
    h = __floats2half2_rn(f0, f1);
    l = __floats2half2_rn(f0 - __half2float(h.x), f1 - __half2float(h.y));
}

// =====================================================================
// Convert kernels
// =====================================================================
__global__ __launch_bounds__(256)
void convx_kernel(const float* __restrict__ X) {
    int i = blockIdx.x * 256 + threadIdx.x;
    float4 v = ((const float4*)X)[i];
    __nv_bfloat162 h0, l0, h1, l1;
    split2(v.x, v.y, h0, l0);
    split2(v.z, v.w, h1, l1);
    ((__nv_bfloat162*)g_Xh)[2 * i] = h0;
    ((__nv_bfloat162*)g_Xh)[2 * i + 1] = h1;
    ((__nv_bfloat162*)g_Xl)[2 * i] = l0;
    ((__nv_bfloat162*)g_Xl)[2 * i + 1] = l1;
}

__global__ __launch_bounds__(256)
void convw_kernel(const float* __restrict__ Wq, const float* __restrict__ Wk,
                  const float* __restrict__ Wv, const float* __restrict__ Wo) {
    int j = blockIdx.x * 256 + threadIdx.x;
    int sel = j >> 13;
    int loc = j & 8191;
    const float* src = (sel == 0) ? Wq : (sel == 1) ? Wk : (sel == 2) ? Wv : Wo;
    __nv_bfloat16* dh = (sel == 0) ? g_Wqh : (sel == 1) ? g_Wkh : (sel == 2) ? g_Wvh : g_Woh;
    __nv_bfloat16* dl = (sel == 0) ? g_Wql : (sel == 1) ? g_Wkl : (sel == 2) ? g_Wvl : g_Wol;
    float4 v = ((const float4*)src)[loc];
    __nv_bfloat162 h0, l0, h1, l1;
    split2(v.x, v.y, h0, l0);
    split2(v.z, v.w, h1, l1);
    ((__nv_bfloat162*)dh)[2 * loc] = h0;
    ((__nv_bfloat162*)dh)[2 * loc + 1] = h1;
    ((__nv_bfloat162*)dl)[2 * loc] = l0;
    ((__nv_bfloat162*)dl)[2 * loc + 1] = l1;
}

// =====================================================================
// Kernel 1: QKV projection via mma.sync, 3xBF16 split.
// grid (128, 3), 256 threads. Q scaled by log2(e); V emitted as fp16 split.
// =====================================================================
#define QKV2_XH 0
#define QKV2_XL 16384
#define QKV2_WH 32768
#define QKV2_WL 49152
#define QKV2_SMEM 65536

__global__ __launch_bounds__(256)
void qkv2_kernel() {
    extern __shared__ char smc[];
    const uint32_t sb = smem_u32(smc);
    const int tid = threadIdx.x;
    const int w = tid >> 5;
    const int lane = tid & 31;
    const int row0 = blockIdx.x * 128;

    const __nv_bfloat16 *WH, *WL;
    if (blockIdx.y == 0)      { WH = g_Wqh; WL = g_Wql; }
    else if (blockIdx.y == 1) { WH = g_Wkh; WL = g_Wkl; }
    else                      { WH = g_Wvh; WL = g_Wvl; }

    const int rowa = 16 * w + (lane & 15);
    const int ca = lane >> 4, swa = rowa & 7;
    const int rowv = (lane & 7) + (lane & 8);
    const int cv = (lane >> 4) & 1, swv = rowv & 7;

    float oacc[16][4];
    #pragma unroll
    for (int nb = 0; nb < 16; nb++)
        #pragma unroll
        for (int i = 0; i < 4; i++) oacc[nb][i] = 0.0f;

    #pragma unroll 1
    for (int kc = 0; kc < 4; kc++) {
        #pragma unroll
        for (int i = 0; i < 4; i++) {
            int lin = tid + i * 256;
            int r = lin >> 3, c = lin & 7;
            uint32_t off = (uint32_t)(r * 128 + ((c ^ (r & 7)) << 4));
            size_t g = (size_t)(row0 + r) * CIN + kc * 64 + c * 8;
            cp16(sb + QKV2_XH + off, g_Xh + g);
            cp16(sb + QKV2_XL + off, g_Xl + g);
        }
        #pragma unroll
        for (int i = 0; i < 4; i++) {
            int lin = tid + i * 256;
            int r = lin >> 4, c = lin & 15;
            uint32_t off = (uint32_t)(r * 256 + ((c ^ (r & 7)) << 4));
            size_t g = (size_t)(kc * 64 + r) * ADIM + c * 8;
            cp16(sb + QKV2_WH + off, WH + g);
            cp16(sb + QKV2_WL + off, WL + g);
        }
        cp_commit(); cp_wait0();
        __syncthreads();
        #pragma unroll
        for (int ks = 0; ks < 4; ks++) {
            uint32_t ah[4], al[4];
            uint32_t ach = (uint32_t)(((2 * ks + ca) ^ swa) << 4);
            ldsm4(ah, sb + QKV2_XH + rowa * 128 + ach);
            ldsm4(al, sb + QKV2_XL + rowa * 128 + ach);
            #pragma unroll
            for (int jp = 0; jp < 8; jp++) {
                uint32_t bh[4], bl[4];
                uint32_t boff = (uint32_t)((16 * ks + rowv) * 256 + (((2 * jp + cv) ^ swv) << 4));
                ldsm4t(bh, sb + QKV2_WH + boff);
                ldsm4t(bl, sb + QKV2_WL + boff);
                mma_bf16(oacc[2 * jp],     ah, bh); mma_bf16(oacc[2 * jp + 1], ah, bh + 2);
                mma_bf16(oacc[2 * jp],     ah, bl); mma_bf16(oacc[2 * jp + 1], ah, bl + 2);
                mma_bf16(oacc[2 * jp],     al, bh); mma_bf16(oacc[2 * jp + 1], al, bh + 2);
            }
        }
        __syncthreads();
    }

    const int r0 = row0 + 16 * w + (lane >> 2);
    const int cb2 = 2 * (lane & 3);
    if (blockIdx.y == 2) {
        // V: fp16 hi/lo split
        #pragma unroll
        for (int nb = 0; nb < 16; nb++) {
            int c = nb * 8 + cb2;
            __half2 h01, l01, h23, l23;
            split2h(lrelu(oacc[nb][0]), lrelu(oacc[nb][1]), h01, l01);
            split2h(lrelu(oacc[nb][2]), lrelu(oacc[nb][3]), h23, l23);
            *(__half2*)&g_Vh[(size_t)r0 * ADIM + c] = h01;
            *(__half2*)&g_Vl[(size_t)r0 * ADIM + c] = l01;
            *(__half2*)&g_Vh[(size_t)(r0 + 8) * ADIM + c] = h23;
            *(__half2*)&g_Vl[(size_t)(r0 + 8) * ADIM + c] = l23;
        }
    } else {
        __nv_bfloat16* OH = (blockIdx.y == 0) ? g_Qh : g_Kh;
        __nv_bfloat16* OL = (blockIdx.y == 0) ? g_Ql : g_Kl;
        const float sc = (blockIdx.y == 0) ? LOG2E : 1.0f;   // Q pre-scaled for ex2
        #pragma unroll
        for (int nb = 0; nb < 16; nb++) {
            int c = nb * 8 + cb2;
            __nv_bfloat162 h01, l01, h23, l23;
            split2(lrelu(oacc[nb][0]) * sc, lrelu(oacc[nb][1]) * sc, h01, l01);
            split2(lrelu(oacc[nb][2]) * sc, lrelu(oacc[nb][3]) * sc, h23, l23);
            *(__nv_bfloat162*)&OH[(size_t)r0 * ADIM + c] = h01;
            *(__nv_bfloat162*)&OL[(size_t)r0 * ADIM + c] = l01;
            *(__nv_bfloat162*)&OH[(size_t)(r0 + 8) * ADIM + c] = h23;
            *(__nv_bfloat162*)&OL[(size_t)(r0 + 8) * ADIM + c] = l23;
        }
    }
}

// =====================================================================
// Kernel 2: flash attention, R5 shape. grid (32,4), 256 threads.
// S: 3-pass bf16 (Q pre-scaled by log2e). PV: 2-pass fp16 (P fp16, V hi/lo fp16).
// smem: Qh 32K | Ql 32K | 2 x {Kh 16K | Kl 16K | Vh 16K | Vl 16K} = 192K
// =====================================================================
#define SQH 0
#define SQL 32768
#define SKV 65536
#define ATTN_SMEM (65536 + 2*65536)

__device__ __forceinline__ void load_kv(uint32_t dst, const __nv_bfloat16* kh,
                                        const __nv_bfloat16* kl, const __half* vh,
                                        const __half* vl, int tid) {
    #pragma unroll
    for (int i = 0; i < 4; i++) {
        int lin = tid + i * 256;
        int r = lin >> 4, c = lin & 15;
        uint32_t off = (uint32_t)(r * 256 + ((c ^ (r & 7)) << 4));
        size_t g = (size_t)r * ADIM + c * 8;
        cp16(dst + off, kh + g);
        cp16(dst + 16384 + off, kl + g);
        cp16(dst + 32768 + off, vh + g);
        cp16(dst + 49152 + off, vl + g);
    }
}

__global__ __launch_bounds__(256, 1)
void attn_kernel() {
    extern __shared__ char smc[];
    const uint32_t sb = smem_u32(smc);
    const int tid = threadIdx.x;
    const int w = tid >> 5;
    const int lane = tid & 31;
    const int b = blockIdx.y;
    const int q0 = blockIdx.x * 128;

    {
        const __nv_bfloat16* qh = g_Qh + (size_t)(b * NTOK + q0) * ADIM;
        const __nv_bfloat16* ql = g_Ql + (size_t)(b * NTOK + q0) * ADIM;
        #pragma unroll
        for (int i = 0; i < 8; i++) {
            int lin = tid + i * 256;
            int r = lin >> 4, c = lin & 15;
            uint32_t off = (uint32_t)(r * 256 + ((c ^ (r & 7)) << 4));
            size_t g = (size_t)r * ADIM + c * 8;
            cp16(sb + SQH + off, qh + g);
            cp16(sb + SQL + off, ql + g);
        }
    }
    const __nv_bfloat16* KHb = g_Kh + (size_t)b * NTOK * ADIM;
    const __nv_bfloat16* KLb = g_Kl + (size_t)b * NTOK * ADIM;
    const __half* VHb = g_Vh + (size_t)b * NTOK * ADIM;
    const __half* VLb = g_Vl + (size_t)b * NTOK * ADIM;
    load_kv(sb + SKV, KHb, KLb, VHb, VLb, tid);
    cp_commit();

    const int rowa = 16 * w + (lane & 15);
    const uint32_t qro = (uint32_t)rowa * 256;
    const int ca = lane >> 4;
    const int swa = rowa & 7;
    const int rowb = (lane & 7) + ((lane & 16) >> 1);
    const int cb = (lane >> 3) & 1;
    const int swb = rowb & 7;
    const int rowv = (lane & 7) + (lane & 8);
    const int cv = (lane >> 4) & 1;
    const int swv = rowv & 7;

    float oacc[16][4];
    #pragma unroll
    for (int nb = 0; nb < 16; nb++)
        #pragma unroll
        for (int i = 0; i < 4; i++) oacc[nb][i] = 0.0f;
    float m0 = -CUDART_INF_F, m8 = -CUDART_INF_F, l0 = 0.0f, l8 = 0.0f;

    #pragma unroll 1
    for (int t = 0; t < 64; t++) {
        __syncthreads();
        if (t < 63) {
            uint32_t nb_ = sb + SKV + (uint32_t)((t + 1) & 1) * 65536u;
            size_t o = (size_t)(t + 1) * 64 * ADIM;
            load_kv(nb_, KHb + o, KLb + o, VHb + o, VLb + o, tid);
            cp_commit();
            cp_wait1();
        } else {
            cp_wait0();
        }
        __syncthreads();

        const uint32_t KB = sb + SKV + (uint32_t)(t & 1) * 65536u;
        const uint32_t VB = KB + 32768u;

        // ---- S = Qh*Kh^T + Qh*Kl^T + Ql*Kh^T (scores already in log2 domain) ----
        float sacc[8][4];
        #pragma unroll
        for (int nb = 0; nb < 8; nb++)
            #pragma unroll
            for (int i = 0; i < 4; i++) sacc[nb][i] = 0.0f;

        #pragma unroll
        for (int ks = 0; ks < 8; ks++) {
            uint32_t aqh[4], aql[4];
            uint32_t ach = (uint32_t)(((2 * ks + ca) ^ swa) << 4);
            ldsm4(aqh, sb + SQH + qro + ach);
            ldsm4(aql, sb + SQL + qro + ach);
            uint32_t bch = (uint32_t)(((2 * ks + cb) ^ swb) << 4);
            #pragma unroll
            for (int jp = 0; jp < 4; jp++) {
                uint32_t bh[4], bl[4];
                uint32_t boff = (uint32_t)((16 * jp + rowb) * 256) + bch;
                ldsm4(bh, KB + boff);
                ldsm4(bl, KB + 16384u + boff);
                mma_bf16(sacc[2 * jp],     aqh, bh);
                mma_bf16(sacc[2 * jp + 1], aqh, bh + 2);
                mma_bf16(sacc[2 * jp],     aqh, bl);
                mma_bf16(sacc[2 * jp + 1], aqh, bl + 2);
                mma_bf16(sacc[2 * jp],     aql, bh);
                mma_bf16(sacc[2 * jp + 1], aql, bh + 2);
            }
        }

        // ---- online softmax (base-2) ----
        float rm0 = sacc[0][0], rm8 = sacc[0][2];
        #pragma unroll
        for (int nb = 0; nb < 8; nb++) {
            rm0 = fmaxf(rm0, fmaxf(sacc[nb][0], sacc[nb][1]));
            rm8 = fmaxf(rm8, fmaxf(sacc[nb][2], sacc[nb][3]));
        }
        rm0 = fmaxf(rm0, __shfl_xor_sync(0xffffffffu, rm0, 1));
        rm0 = fmaxf(rm0, __shfl_xor_sync(0xffffffffu, rm0, 2));
        rm8 = fmaxf(rm8, __shfl_xor_sync(0xffffffffu, rm8, 1));
        rm8 = fmaxf(rm8, __shfl_xor_sync(0xffffffffu, rm8, 2));
        float mn0 = fmaxf(m0, rm0), mn8 = fmaxf(m8, rm8);
        float sc0 = ex2(m0 - mn0), sc8 = ex2(m8 - mn8);
        m0 = mn0; m8 = mn8;

        uint32_t ph[8][2];
        float ls0 = 0.0f, ls8 = 0.0f;
        #pragma unroll
        for (int nb = 0; nb < 8; nb++) {
            float p0 = ex2(sacc[nb][0] - mn0);
            float p1 = ex2(sacc[nb][1] - mn0);
            float p2 = ex2(sacc[nb][2] - mn8);
            float p3 = ex2(sacc[nb][3] - mn8);
            ls0 += p0 + p1; ls8 += p2 + p3;
            ph[nb][0] = h2bits(__floats2half2_rn(p0, p1));
            ph[nb][1] = h2bits(__floats2half2_rn(p2, p3));
        }
        l0 = l0 * sc0 + ls0;
        l8 = l8 * sc8 + ls8;
        if (sc0 < 1.0f) {
            #pragma unroll
            for (int nb = 0; nb < 16; nb++) { oacc[nb][0] *= sc0; oacc[nb][1] *= sc0; }
        }
        if (sc8 < 1.0f) {
            #pragma unroll
            for (int nb = 0; nb < 16; nb++) { oacc[nb][2] *= sc8; oacc[nb][3] *= sc8; }
        }

        // ---- O += P*Vh + P*Vl (fp16, 2 passes) ----
        #pragma unroll
        for (int ks = 0; ks < 4; ks++) {
            uint32_t ah[4] = { ph[2 * ks][0], ph[2 * ks][1], ph[2 * ks + 1][0], ph[2 * ks + 1][1] };
            uint32_t vro = (uint32_t)((16 * ks + rowv) * 256);
            #pragma unroll
            for (int jp = 0; jp < 8; jp++) {
                uint32_t bh[4], bl[4];
                uint32_t voff = vro + (uint32_t)(((2 * jp + cv) ^ swv) << 4);
                ldsm4t(bh, VB + voff);
                ldsm4t(bl, VB + 16384u + voff);
                mma_f16(oacc[2 * jp],     ah, bh);
                mma_f16(oacc[2 * jp + 1], ah, bh + 2);
                mma_f16(oacc[2 * jp],     ah, bl);
                mma_f16(oacc[2 * jp + 1], ah, bl + 2);
            }
        }
    }

    // ---- epilogue: normalize, split to bf16 hi/lo ----
    l0 += __shfl_xor_sync(0xffffffffu, l0, 1);
    l0 += __shfl_xor_sync(0xffffffffu, l0, 2);
    l8 += __shfl_xor_sync(0xffffffffu, l8, 1);
    l8 += __shfl_xor_sync(0xffffffffu, l8, 2);
    float inv0 = 1.0f / l0, inv8 = 1.0f / l8;
    size_t r0 = (size_t)b * NTOK + q0 + 16 * w + (lane >> 2);
    int cb2 = 2 * (lane & 3);
    #pragma unroll
    for (int nb = 0; nb < 16; nb++) {
        int c = nb * 8 + cb2;
        __nv_bfloat162 h01, l01, h23, l23;
        split2(oacc[nb][0] * inv0, oacc[nb][1] * inv0, h01, l01);
        split2(oacc[nb][2] * inv8, oacc[nb][3] * inv8, h23, l23);
        *(__nv_bfloat162*)&g_Oh[r0 * ADIM + c] = h01;
        *(__nv_bfloat162*)&g_Ol[r0 * ADIM + c] = l01;
        *(__nv_bfloat162*)&g_Oh[(r0 + 8) * ADIM + c] = h23;
        *(__nv_bfloat162*)&g_Ol[(r0 + 8) * ADIM + c] = l23;
    }
}

// =====================================================================
// Kernel 3: Y = O @ Wo * tanh(relu(1+wg)) via mma.sync, 3xBF16 split.
// grid (128, 2), 256 threads.
// =====================================================================
#define OUT2_AH 0
#define OUT2_AL 16384
#define OUT2_WH 32768
#define OUT2_WL 49152
#define OUT2_SMEM 65536

__global__ __launch_bounds__(256)
void out2_kernel(const float* __restrict__ wgm, float* __restrict__ Y) {
    extern __shared__ char smc[];
    const uint32_t sb = smem_u32(smc);
    const int tid = threadIdx.x;
    const int w = tid >> 5;
    const int lane = tid & 31;
    const int row0 = blockIdx.x * 128;
    const int col0 = blockIdx.y * 128;

    const int rowa = 16 * w + (lane & 15);
    const int ca = lane >> 4, swa = rowa & 7;
    const int rowv = (lane & 7) + (lane & 8);
    const int cv = (lane >> 4) & 1, swv = rowv & 7;

    float oacc[16][4];
    #pragma unroll
    for (int nb = 0; nb < 16; nb++)
        #pragma unroll
        for (int i = 0; i < 4; i++) oacc[nb][i] = 0.0f;

    #pragma unroll 1
    for (int kc = 0; kc < 2; kc++) {
        #pragma unroll
        for (int i = 0; i < 4; i++) {
            int lin = tid + i * 256;
            int r = lin >> 3, c = lin & 7;
            uint32_t off = (uint32_t)(r * 128 + ((c ^ (r & 7)) << 4));
            size_t g = (size_t)(row0 + r) * ADIM + kc * 64 + c * 8;
            cp16(sb + OUT2_AH + off, g_Oh + g);
            cp16(sb + OUT2_AL + off, g_Ol + g);
        }
        #pragma unroll
        for (int i = 0; i < 4; i++) {
            int lin = tid + i * 256;
            int r = lin >> 4, c = lin & 15;
            uint32_t off = (uint32_t)(r * 256 + ((c ^ (r & 7)) << 4));
            size_t g = (size_t)(kc * 64 + r) * CIN + col0 + c * 8;
            cp16(sb + OUT2_WH + off, g_Woh + g);
            cp16(sb + OUT2_WL + off, g_Wol + g);
        }
        cp_commit(); cp_wait0();
        __syncthreads();
        #pragma unroll
        for (int ks = 0; ks < 4; ks++) {
            uint32_t ah[4], al[4];
            uint32_t ach = (uint32_t)(((2 * ks + ca) ^ swa) << 4);
            ldsm4(ah, sb + OUT2_AH + rowa * 128 + ach);
            ldsm4(al, sb + OUT2_AL + rowa * 128 + ach);
            #pragma unroll
            for (int jp = 0; jp < 8; jp++) {
                uint32_t bh[4], bl[4];
                uint32_t boff = (uint32_t)((16 * ks + rowv) * 256 + (((2 * jp + cv) ^ swv) << 4));
                ldsm4t(bh, sb + OUT2_WH + boff);
                ldsm4t(bl, sb + OUT2_WL + boff);
                mma_bf16(oacc[2 * jp],     ah, bh); mma_bf16(oacc[2 * jp + 1], ah, bh + 2);
                mma_bf16(oacc[2 * jp],     ah, bl); mma_bf16(oacc[2 * jp + 1], ah, bl + 2);
                mma_bf16(oacc[2 * jp],     al, bh); mma_bf16(oacc[2 * jp + 1], al, bh + 2);
            }
        }
        __syncthreads();
    }

    const int r0 = row0 + 16 * w + (lane >> 2);
    const int cb2 = 2 * (lane & 3);
    #pragma unroll
    for (int nb = 0; nb < 16; nb++) {
        int c = col0 + nb * 8 + cb2;
        float g0 = tanhf(fmaxf(1.0f + wgm[c], 0.0f));
        float g1 = tanhf(fmaxf(1.0f + wgm[c + 1], 0.0f));
        *(float2*)&Y[(size_t)r0 * CIN + c] =
            make_float2(oacc[nb][0] * g0, oacc[nb][1] * g1);
        *(float2*)&Y[(size_t)(r0 + 8) * CIN + c] =
            make_float2(oacc[nb][2] * g0, oacc[nb][3] * g1);
    }
}

// =====================================================================
extern "C" void kernel_launch(void* const* d_in, const int* in_sizes, int n_in,
                              void* d_out, int out_size) {
    const float* x  = (const float*)d_in[0];
    const float* Wq = (const float*)d_in[1];
    const float* Wk = (const float*)d_in[2];
    const float* Wv = (const float*)d_in[3];
    const float* Wo = (const float*)d_in[4];
    const float* wg = (const float*)d_in[5];
    float* y = (float*)d_out;

    static bool attrs_set = []() {
        cudaFuncSetAttribute(qkv2_kernel, cudaFuncAttributeMaxDynamicSharedMemorySize, QKV2_SMEM);
        cudaFuncSetAttribute(attn_kernel, cudaFuncAttributeMaxDynamicSharedMemorySize, ATTN_SMEM);
        cudaFuncSetAttribute(out2_kernel, cudaFuncAttributeMaxDynamicSharedMemorySize, OUT2_SMEM);
        return true;
    }();
    (void)attrs_set;

    convx_kernel<<<4096, 256>>>(x);
    convw_kernel<<<128, 256>>>(Wq, Wk, Wv, Wo);
    qkv2_kernel<<<dim3(128, 3), 256, QKV2_SMEM>>>();
    attn_kernel<<<dim3(NTOK / 128, BATCH), 256, ATTN_SMEM>>>();
    out2_kernel<<<dim3(128, 2), 256, OUT2_SMEM>>>(wg, y);
}

// round 9
// speedup vs baseline: 1.3343x; 1.1597x over previous
#include <cuda_runtime.h>
#include <cuda_bf16.h>
#include <cuda_fp16.h>
#include <math_constants.h>
#include <stdint.h>

#define BATCH 4
#define NTOK 4096
#define CIN 256
#define ADIM 128
#define MTOT (BATCH*NTOK)
#define NEG_SLOPE 0.2f
#define LOG2E 1.4426950408889634f

// ---------------- scratch ----------------
__device__ __nv_bfloat16 g_Xh[MTOT * CIN];
__device__ __nv_bfloat16 g_Xl[MTOT * CIN];
__device__ __nv_bfloat16 g_Qh[MTOT * ADIM];   // pre-scaled by log2(e)
__device__ __nv_bfloat16 g_Ql[MTOT * ADIM];
__device__ __nv_bfloat16 g_Kh[MTOT * ADIM];
__device__ __nv_bfloat16 g_Kl[MTOT * ADIM];
__device__ __half        g_V[MTOT * ADIM];    // single fp16 (P is fp16 anyway)
__device__ __nv_bfloat16 g_Oh[MTOT * ADIM];
__device__ __nv_bfloat16 g_Ol[MTOT * ADIM];
__device__ __nv_bfloat16 g_Wqh[CIN * ADIM], g_Wql[CIN * ADIM];
__device__ __nv_bfloat16 g_Wkh[CIN * ADIM], g_Wkl[CIN * ADIM];
__device__ __nv_bfloat16 g_Wvh[CIN * ADIM], g_Wvl[CIN * ADIM];
__device__ __nv_bfloat16 g_Woh[ADIM * CIN], g_Wol[ADIM * CIN];

__device__ __forceinline__ float lrelu(float x) { return x >= 0.0f ? x : NEG_SLOPE * x; }

// ---------------- helpers ----------------
__device__ __forceinline__ uint32_t smem_u32(const void* p) {
    uint32_t a;
    asm("{ .reg .u64 t; cvta.to.shared.u64 t, %1; cvt.u32.u64 %0, t; }" : "=r"(a) : "l"(p));
    return a;
}
__device__ __forceinline__ void cp16(uint32_t dst, const void* src) {
    asm volatile("cp.async.cg.shared.global [%0], [%1], 16;" :: "r"(dst), "l"(src));
}
__device__ __forceinline__ void cp_commit() { asm volatile("cp.async.commit_group;" ::: "memory"); }
__device__ __forceinline__ void cp_wait0() { asm volatile("cp.async.wait_group 0;" ::: "memory"); }
__device__ __forceinline__ void cp_wait1() { asm volatile("cp.async.wait_group 1;" ::: "memory"); }

__device__ __forceinline__ void ldsm4(uint32_t* r, uint32_t a) {
    asm volatile("ldmatrix.sync.aligned.m8n8.x4.shared.b16 {%0,%1,%2,%3}, [%4];"
        : "=r"(r[0]), "=r"(r[1]), "=r"(r[2]), "=r"(r[3]) : "r"(a));
}
__device__ __forceinline__ void ldsm4t(uint32_t* r, uint32_t a) {
    asm volatile("ldmatrix.sync.aligned.m8n8.x4.trans.shared.b16 {%0,%1,%2,%3}, [%4];"
        : "=r"(r[0]), "=r"(r[1]), "=r"(r[2]), "=r"(r[3]) : "r"(a));
}
__device__ __forceinline__ void mma_bf16(float* d, const uint32_t* a, const uint32_t* b) {
    asm volatile(
        "mma.sync.aligned.m16n8k16.row.col.f32.bf16.bf16.f32 "
        "{%0,%1,%2,%3}, {%4,%5,%6,%7}, {%8,%9}, {%0,%1,%2,%3};"
        : "+f"(d[0]), "+f"(d[1]), "+f"(d[2]), "+f"(d[3])
        : "r"(a[0]), "r"(a[1]), "r"(a[2]), "r"(a[3]), "r"(b[0]), "r"(b[1]));
}
__device__ __forceinline__ void mma_f16(float* d, const uint32_t* a, const uint32_t* b) {
    asm volatile(
        "mma.sync.aligned.m16n8k16.row.col.f32.f16.f16.f32 "
        "{%0,%1,%2,%3}, {%4,%5,%6,%7}, {%8,%9}, {%0,%1,%2,%3};"
        : "+f"(d[0]), "+f"(d[1]), "+f"(d[2]), "+f"(d[3])
        : "r"(a[0]), "r"(a[1]), "r"(a[2]), "r"(a[3]), "r"(b[0]), "r"(b[1]));
}
__device__ __forceinline__ uint32_t h2bits(__half2 v) { return *(uint32_t*)&v; }
__device__ __forceinline__ float ex2(float x) {
    float r; asm("ex2.approx.f32 %0, %1;" : "=f"(r) : "f"(x)); return r;
}

__device__ __forceinline__ void split2(float f0, float f1, __nv_bfloat162& h, __nv_bfloat162& l) {
    h = __floats2bfloat162_rn(f0, f1);
    l = __floats2bfloat162_rn(f0 - __bfloat162float(h.x), f1 - __bfloat162float(h.y));
}

// =====================================================================
// Convert kernels
// =====================================================================
__global__ __launch_bounds__(256)
void convx_kernel(const float* __restrict__ X) {
    int i = blockIdx.x * 256 + threadIdx.x;
    float4 v = ((const float4*)X)[i];
    __nv_bfloat162 h0, l0, h1, l1;
    split2(v.x, v.y, h0, l0);
    split2(v.z, v.w, h1, l1);
    ((__nv_bfloat162*)g_Xh)[2 * i] = h0;
    ((__nv_bfloat162*)g_Xh)[2 * i + 1] = h1;
    ((__nv_bfloat162*)g_Xl)[2 * i] = l0;
    ((__nv_bfloat162*)g_Xl)[2 * i + 1] = l1;
}

__global__ __launch_bounds__(256)
void convw_kernel(const float* __restrict__ Wq, const float* __restrict__ Wk,
                  const float* __restrict__ Wv, const float* __restrict__ Wo) {
    int j = blockIdx.x * 256 + threadIdx.x;
    int sel = j >> 13;
    int loc = j & 8191;
    const float* src = (sel == 0) ? Wq : (sel == 1) ? Wk : (sel == 2) ? Wv : Wo;
    __nv_bfloat16* dh = (sel == 0) ? g_Wqh : (sel == 1) ? g_Wkh : (sel == 2) ? g_Wvh : g_Woh;
    __nv_bfloat16* dl = (sel == 0) ? g_Wql : (sel == 1) ? g_Wkl : (sel == 2) ? g_Wvl : g_Wol;
    float4 v = ((const float4*)src)[loc];
    __nv_bfloat162 h0, l0, h1, l1;
    split2(v.x, v.y, h0, l0);
    split2(v.z, v.w, h1, l1);
    ((__nv_bfloat162*)dh)[2 * loc] = h0;
    ((__nv_bfloat162*)dh)[2 * loc + 1] = h1;
    ((__nv_bfloat162*)dl)[2 * loc] = l0;
    ((__nv_bfloat162*)dl)[2 * loc + 1] = l1;
}

// =====================================================================
// Kernel 1: QKV projection via mma.sync, 3xBF16 split.
// grid (128, 3), 256 threads. Q scaled by log2(e); V emitted as single fp16.
// =====================================================================
#define QKV2_XH 0
#define QKV2_XL 16384
#define QKV2_WH 32768
#define QKV2_WL 49152
#define QKV2_SMEM 65536

__global__ __launch_bounds__(256)
void qkv2_kernel() {
    extern __shared__ char smc[];
    const uint32_t sb = smem_u32(smc);
    const int tid = threadIdx.x;
    const int w = tid >> 5;
    const int lane = tid & 31;
    const int row0 = blockIdx.x * 128;

    const __nv_bfloat16 *WH, *WL;
    if (blockIdx.y == 0)      { WH = g_Wqh; WL = g_Wql; }
    else if (blockIdx.y == 1) { WH = g_Wkh; WL = g_Wkl; }
    else                      { WH = g_Wvh; WL = g_Wvl; }

    const int rowa = 16 * w + (lane & 15);
    const int ca = lane >> 4, swa = rowa & 7;
    const int rowv = (lane & 7) + (lane & 8);
    const int cv = (lane >> 4) & 1, swv = rowv & 7;

    float oacc[16][4];
    #pragma unroll
    for (int nb = 0; nb < 16; nb++)
        #pragma unroll
        for (int i = 0; i < 4; i++) oacc[nb][i] = 0.0f;

    #pragma unroll 1
    for (int kc = 0; kc < 4; kc++) {
        #pragma unroll
        for (int i = 0; i < 4; i++) {
            int lin = tid + i * 256;
            int r = lin >> 3, c = lin & 7;
            uint32_t off = (uint32_t)(r * 128 + ((c ^ (r & 7)) << 4));
            size_t g = (size_t)(row0 + r) * CIN + kc * 64 + c * 8;
            cp16(sb + QKV2_XH + off, g_Xh + g);
            cp16(sb + QKV2_XL + off, g_Xl + g);
        }
        #pragma unroll
        for (int i = 0; i < 4; i++) {
            int lin = tid + i * 256;
            int r = lin >> 4, c = lin & 15;
            uint32_t off = (uint32_t)(r * 256 + ((c ^ (r & 7)) << 4));
            size_t g = (size_t)(kc * 64 + r) * ADIM + c * 8;
            cp16(sb + QKV2_WH + off, WH + g);
            cp16(sb + QKV2_WL + off, WL + g);
        }
        cp_commit(); cp_wait0();
        __syncthreads();
        #pragma unroll
        for (int ks = 0; ks < 4; ks++) {
            uint32_t ah[4], al[4];
            uint32_t ach = (uint32_t)(((2 * ks + ca) ^ swa) << 4);
            ldsm4(ah, sb + QKV2_XH + rowa * 128 + ach);
            ldsm4(al, sb + QKV2_XL + rowa * 128 + ach);
            #pragma unroll
            for (int jp = 0; jp < 8; jp++) {
                uint32_t bh[4], bl[4];
                uint32_t boff = (uint32_t)((16 * ks + rowv) * 256 + (((2 * jp + cv) ^ swv) << 4));
                ldsm4t(bh, sb + QKV2_WH + boff);
                ldsm4t(bl, sb + QKV2_WL + boff);
                mma_bf16(oacc[2 * jp],     ah, bh); mma_bf16(oacc[2 * jp + 1], ah, bh + 2);
                mma_bf16(oacc[2 * jp],     ah, bl); mma_bf16(oacc[2 * jp + 1], ah, bl + 2);
                mma_bf16(oacc[2 * jp],     al, bh); mma_bf16(oacc[2 * jp + 1], al, bh + 2);
            }
        }
        __syncthreads();
    }

    const int r0 = row0 + 16 * w + (lane >> 2);
    const int cb2 = 2 * (lane & 3);
    if (blockIdx.y == 2) {
        // V: single fp16 (P is fp16 in PV anyway; lo half adds nothing)
        #pragma unroll
        for (int nb = 0; nb < 16; nb++) {
            int c = nb * 8 + cb2;
            *(__half2*)&g_V[(size_t)r0 * ADIM + c] =
                __floats2half2_rn(lrelu(oacc[nb][0]), lrelu(oacc[nb][1]));
            *(__half2*)&g_V[(size_t)(r0 + 8) * ADIM + c] =
                __floats2half2_rn(lrelu(oacc[nb][2]), lrelu(oacc[nb][3]));
        }
    } else {
        __nv_bfloat16* OH = (blockIdx.y == 0) ? g_Qh : g_Kh;
        __nv_bfloat16* OL = (blockIdx.y == 0) ? g_Ql : g_Kl;
        const float sc = (blockIdx.y == 0) ? LOG2E : 1.0f;
        #pragma unroll
        for (int nb = 0; nb < 16; nb++) {
            int c = nb * 8 + cb2;
            __nv_bfloat162 h01, l01, h23, l23;
            split2(lrelu(oacc[nb][0]) * sc, lrelu(oacc[nb][1]) * sc, h01, l01);
            split2(lrelu(oacc[nb][2]) * sc, lrelu(oacc[nb][3]) * sc, h23, l23);
            *(__nv_bfloat162*)&OH[(size_t)r0 * ADIM + c] = h01;
            *(__nv_bfloat162*)&OL[(size_t)r0 * ADIM + c] = l01;
            *(__nv_bfloat162*)&OH[(size_t)(r0 + 8) * ADIM + c] = h23;
            *(__nv_bfloat162*)&OL[(size_t)(r0 + 8) * ADIM + c] = l23;
        }
    }
}

// =====================================================================
// Kernel 2: flash attention. grid (32,4), 256 threads.
// S: 3-pass bf16 (log2 domain). PV: 1-pass fp16.
// smem: Qh 32K | Ql 32K | 2 x {Kh 16K | Kl 16K | V 16K} = 160K
// =====================================================================
#define SQH 0
#define SQL 32768
#define SKV 65536
#define KVBUF 49152
#define ATTN_SMEM (65536 + 2*KVBUF)

__device__ __forceinline__ void load_kv(uint32_t dst, const __nv_bfloat16* kh,
                                        const __nv_bfloat16* kl, const __half* v, int tid) {
    #pragma unroll
    for (int i = 0; i < 4; i++) {
        int lin = tid + i * 256;
        int r = lin >> 4, c = lin & 15;
        uint32_t off = (uint32_t)(r * 256 + ((c ^ (r & 7)) << 4));
        size_t g = (size_t)r * ADIM + c * 8;
        cp16(dst + off, kh + g);
        cp16(dst + 16384 + off, kl + g);
        cp16(dst + 32768 + off, v + g);
    }
}

__global__ __launch_bounds__(256, 1)
void attn_kernel() {
    extern __shared__ char smc[];
    const uint32_t sb = smem_u32(smc);
    const int tid = threadIdx.x;
    const int w = tid >> 5;
    const int lane = tid & 31;
    const int b = blockIdx.y;
    const int q0 = blockIdx.x * 128;

    {
        const __nv_bfloat16* qh = g_Qh + (size_t)(b * NTOK + q0) * ADIM;
        const __nv_bfloat16* ql = g_Ql + (size_t)(b * NTOK + q0) * ADIM;
        #pragma unroll
        for (int i = 0; i < 8; i++) {
            int lin = tid + i * 256;
            int r = lin >> 4, c = lin & 15;
            uint32_t off = (uint32_t)(r * 256 + ((c ^ (r & 7)) << 4));
            size_t g = (size_t)r * ADIM + c * 8;
            cp16(sb + SQH + off, qh + g);
            cp16(sb + SQL + off, ql + g);
        }
    }
    const __nv_bfloat16* KHb = g_Kh + (size_t)b * NTOK * ADIM;
    const __nv_bfloat16* KLb = g_Kl + (size_t)b * NTOK * ADIM;
    const __half* Vb = g_V + (size_t)b * NTOK * ADIM;
    load_kv(sb + SKV, KHb, KLb, Vb, tid);
    cp_commit();

    const int rowa = 16 * w + (lane & 15);
    const uint32_t qro = (uint32_t)rowa * 256;
    const int ca = lane >> 4;
    const int swa = rowa & 7;
    const int rowb = (lane & 7) + ((lane & 16) >> 1);
    const int cb = (lane >> 3) & 1;
    const int swb = rowb & 7;
    const int rowv = (lane & 7) + (lane & 8);
    const int cv = (lane >> 4) & 1;
    const int swv = rowv & 7;

    float oacc[16][4];
    #pragma unroll
    for (int nb = 0; nb < 16; nb++)
        #pragma unroll
        for (int i = 0; i < 4; i++) oacc[nb][i] = 0.0f;
    float m0 = -CUDART_INF_F, m8 = -CUDART_INF_F, l0 = 0.0f, l8 = 0.0f;

    #pragma unroll 1
    for (int t = 0; t < 64; t++) {
        __syncthreads();
        if (t < 63) {
            uint32_t nb_ = sb + SKV + (uint32_t)((t + 1) & 1) * (uint32_t)KVBUF;
            size_t o = (size_t)(t + 1) * 64 * ADIM;
            load_kv(nb_, KHb + o, KLb + o, Vb + o, tid);
            cp_commit();
            cp_wait1();
        } else {
            cp_wait0();
        }
        __syncthreads();

        const uint32_t KB = sb + SKV + (uint32_t)(t & 1) * (uint32_t)KVBUF;
        const uint32_t VB = KB + 32768u;

        // ---- S = Qh*Kh^T + Qh*Kl^T + Ql*Kh^T (log2 domain) ----
        float sacc[8][4];
        #pragma unroll
        for (int nb = 0; nb < 8; nb++)
            #pragma unroll
            for (int i = 0; i < 4; i++) sacc[nb][i] = 0.0f;

        #pragma unroll
        for (int ks = 0; ks < 8; ks++) {
            uint32_t aqh[4], aql[4];
            uint32_t ach = (uint32_t)(((2 * ks + ca) ^ swa) << 4);
            ldsm4(aqh, sb + SQH + qro + ach);
            ldsm4(aql, sb + SQL + qro + ach);
            uint32_t bch = (uint32_t)(((2 * ks + cb) ^ swb) << 4);
            #pragma unroll
            for (int jp = 0; jp < 4; jp++) {
                uint32_t bh[4], bl[4];
                uint32_t boff = (uint32_t)((16 * jp + rowb) * 256) + bch;
                ldsm4(bh, KB + boff);
                ldsm4(bl, KB + 16384u + boff);
                mma_bf16(sacc[2 * jp],     aqh, bh);
                mma_bf16(sacc[2 * jp + 1], aqh, bh + 2);
                mma_bf16(sacc[2 * jp],     aqh, bl);
                mma_bf16(sacc[2 * jp + 1], aqh, bl + 2);
                mma_bf16(sacc[2 * jp],     aql, bh);
                mma_bf16(sacc[2 * jp + 1], aql, bh + 2);
            }
        }

        // ---- online softmax (base-2) ----
        float rm0 = sacc[0][0], rm8 = sacc[0][2];
        #pragma unroll
        for (int nb = 0; nb < 8; nb++) {
            rm0 = fmaxf(rm0, fmaxf(sacc[nb][0], sacc[nb][1]));
            rm8 = fmaxf(rm8, fmaxf(sacc[nb][2], sacc[nb][3]));
        }
        rm0 = fmaxf(rm0, __shfl_xor_sync(0xffffffffu, rm0, 1));
        rm0 = fmaxf(rm0, __shfl_xor_sync(0xffffffffu, rm0, 2));
        rm8 = fmaxf(rm8, __shfl_xor_sync(0xffffffffu, rm8, 1));
        rm8 = fmaxf(rm8, __shfl_xor_sync(0xffffffffu, rm8, 2));
        float mn0 = fmaxf(m0, rm0), mn8 = fmaxf(m8, rm8);
        float sc0 = ex2(m0 - mn0), sc8 = ex2(m8 - mn8);
        m0 = mn0; m8 = mn8;

        uint32_t ph[8][2];
        float ls0 = 0.0f, ls8 = 0.0f;
        #pragma unroll
        for (int nb = 0; nb < 8; nb++) {
            float p0 = ex2(sacc[nb][0] - mn0);
            float p1 = ex2(sacc[nb][1] - mn0);
            float p2 = ex2(sacc[nb][2] - mn8);
            float p3 = ex2(sacc[nb][3] - mn8);
            ls0 += p0 + p1; ls8 += p2 + p3;
            ph[nb][0] = h2bits(__floats2half2_rn(p0, p1));
            ph[nb][1] = h2bits(__floats2half2_rn(p2, p3));
        }
        l0 = l0 * sc0 + ls0;
        l8 = l8 * sc8 + ls8;
        if (sc0 < 1.0f) {
            #pragma unroll
            for (int nb = 0; nb < 16; nb++) { oacc[nb][0] *= sc0; oacc[nb][1] *= sc0; }
        }
        if (sc8 < 1.0f) {
            #pragma unroll
            for (int nb = 0; nb < 16; nb++) { oacc[nb][2] *= sc8; oacc[nb][3] *= sc8; }
        }

        // ---- O += P*V (single fp16 pass) ----
        #pragma unroll
        for (int ks = 0; ks < 4; ks++) {
            uint32_t ah[4] = { ph[2 * ks][0], ph[2 * ks][1], ph[2 * ks + 1][0], ph[2 * ks + 1][1] };
            uint32_t vro = (uint32_t)((16 * ks + rowv) * 256);
            #pragma unroll
            for (int jp = 0; jp < 8; jp++) {
                uint32_t bh[4];
                uint32_t voff = vro + (uint32_t)(((2 * jp + cv) ^ swv) << 4);
                ldsm4t(bh, VB + voff);
                mma_f16(oacc[2 * jp],     ah, bh);
                mma_f16(oacc[2 * jp + 1], ah, bh + 2);
            }
        }
    }

    // ---- epilogue: normalize, split to bf16 hi/lo ----
    l0 += __shfl_xor_sync(0xffffffffu, l0, 1);
    l0 += __shfl_xor_sync(0xffffffffu, l0, 2);
    l8 += __shfl_xor_sync(0xffffffffu, l8, 1);
    l8 += __shfl_xor_sync(0xffffffffu, l8, 2);
    float inv0 = 1.0f / l0, inv8 = 1.0f / l8;
    size_t r0 = (size_t)b * NTOK + q0 + 16 * w + (lane >> 2);
    int cb2 = 2 * (lane & 3);
    #pragma unroll
    for (int nb = 0; nb < 16; nb++) {
        int c = nb * 8 + cb2;
        __nv_bfloat162 h01, l01, h23, l23;
        split2(oacc[nb][0] * inv0, oacc[nb][1] * inv0, h01, l01);
        split2(oacc[nb][2] * inv8, oacc[nb][3] * inv8, h23, l23);
        *(__nv_bfloat162*)&g_Oh[r0 * ADIM + c] = h01;
        *(__nv_bfloat162*)&g_Ol[r0 * ADIM + c] = l01;
        *(__nv_bfloat162*)&g_Oh[(r0 + 8) * ADIM + c] = h23;
        *(__nv_bfloat162*)&g_Ol[(r0 + 8) * ADIM + c] = l23;
    }
}

// =====================================================================
// Kernel 3: Y = O @ Wo * tanh(relu(1+wg)) via mma.sync, 3xBF16 split.
// grid (128, 2), 256 threads.
// =====================================================================
#define OUT2_AH 0
#define OUT2_AL 16384
#define OUT2_WH 32768
#define OUT2_WL 49152
#define OUT2_SMEM 65536

__global__ __launch_bounds__(256)
void out2_kernel(const float* __restrict__ wgm, float* __restrict__ Y) {
    extern __shared__ char smc[];
    const uint32_t sb = smem_u32(smc);
    const int tid = threadIdx.x;
    const int w = tid >> 5;
    const int lane = tid & 31;
    const int row0 = blockIdx.x * 128;
    const int col0 = blockIdx.y * 128;

    const int rowa = 16 * w + (lane & 15);
    const int ca = lane >> 4, swa = rowa & 7;
    const int rowv = (lane & 7) + (lane & 8);
    const int cv = (lane >> 4) & 1, swv = rowv & 7;

    float oacc[16][4];
    #pragma unroll
    for (int nb = 0; nb < 16; nb++)
        #pragma unroll
        for (int i = 0; i < 4; i++) oacc[nb][i] = 0.0f;

    #pragma unroll 1
    for (int kc = 0; kc < 2; kc++) {
        #pragma unroll
        for (int i = 0; i < 4; i++) {
            int lin = tid + i * 256;
            int r = lin >> 3, c = lin & 7;
            uint32_t off = (uint32_t)(r * 128 + ((c ^ (r & 7)) << 4));
            size_t g = (size_t)(row0 + r) * ADIM + kc * 64 + c * 8;
            cp16(sb + OUT2_AH + off, g_Oh + g);
            cp16(sb + OUT2_AL + off, g_Ol + g);
        }
        #pragma unroll
        for (int i = 0; i < 4; i++) {
            int lin = tid + i * 256;
            int r = lin >> 4, c = lin & 15;
            uint32_t off = (uint32_t)(r * 256 + ((c ^ (r & 7)) << 4));
            size_t g = (size_t)(kc * 64 + r) * CIN + col0 + c * 8;
            cp16(sb + OUT2_WH + off, g_Woh + g);
            cp16(sb + OUT2_WL + off, g_Wol + g);
        }
        cp_commit(); cp_wait0();
        __syncthreads();
        #pragma unroll
        for (int ks = 0; ks < 4; ks++) {
            uint32_t ah[4], al[4];
            uint32_t ach = (uint32_t)(((2 * ks + ca) ^ swa) << 4);
            ldsm4(ah, sb + OUT2_AH + rowa * 128 + ach);
            ldsm4(al, sb + OUT2_AL + rowa * 128 + ach);
            #pragma unroll
            for (int jp = 0; jp < 8; jp++) {
                uint32_t bh[4], bl[4];
                uint32_t boff = (uint32_t)((16 * ks + rowv) * 256 + (((2 * jp + cv) ^ swv) << 4));
                ldsm4t(bh, sb + OUT2_WH + boff);
                ldsm4t(bl, sb + OUT2_WL + boff);
                mma_bf16(oacc[2 * jp],     ah, bh); mma_bf16(oacc[2 * jp + 1], ah, bh + 2);
                mma_bf16(oacc[2 * jp],     ah, bl); mma_bf16(oacc[2 * jp + 1], ah, bl + 2);
                mma_bf16(oacc[2 * jp],     al, bh); mma_bf16(oacc[2 * jp + 1], al, bh + 2);
            }
        }
        __syncthreads();
    }

    const int r0 = row0 + 16 * w + (lane >> 2);
    const int cb2 = 2 * (lane & 3);
    #pragma unroll
    for (int nb = 0; nb < 16; nb++) {
        int c = col0 + nb * 8 + cb2;
        float g0 = tanhf(fmaxf(1.0f + wgm[c], 0.0f));
        float g1 = tanhf(fmaxf(1.0f + wgm[c + 1], 0.0f));
        *(float2*)&Y[(size_t)r0 * CIN + c] =
            make_float2(oacc[nb][0] * g0, oacc[nb][1] * g1);
        *(float2*)&Y[(size_t)(r0 + 8) * CIN + c] =
            make_float2(oacc[nb][2] * g0, oacc[nb][3] * g1);
    }
}

// =====================================================================
extern "C" void kernel_launch(void* const* d_in, const int* in_sizes, int n_in,
                              void* d_out, int out_size) {
    const float* x  = (const float*)d_in[0];
    const float* Wq = (const float*)d_in[1];
    const float* Wk = (const float*)d_in[2];
    const float* Wv = (const float*)d_in[3];
    const float* Wo = (const float*)d_in[4];
    const float* wg = (const float*)d_in[5];
    float* y = (float*)d_out;

    static bool attrs_set = []() {
        cudaFuncSetAttribute(qkv2_kernel, cudaFuncAttributeMaxDynamicSharedMemorySize, QKV2_SMEM);
        cudaFuncSetAttribute(attn_kernel, cudaFuncAttributeMaxDynamicSharedMemorySize, ATTN_SMEM);
        cudaFuncSetAttribute(out2_kernel, cudaFuncAttributeMaxDynamicSharedMemorySize, OUT2_SMEM);
        return true;
    }();
    (void)attrs_set;

    convx_kernel<<<4096, 256>>>(x);
    convw_kernel<<<128, 256>>>(Wq, Wk, Wv, Wo);
    qkv2_kernel<<<dim3(128, 3), 256, QKV2_SMEM>>>();
    attn_kernel<<<dim3(NTOK / 128, BATCH), 256, ATTN_SMEM>>>();
    out2_kernel<<<dim3(128, 2), 256, OUT2_SMEM>>>(wg, y);
}

// round 10
// speedup vs baseline: 1.3682x; 1.0254x over previous
#include <cuda_runtime.h>
#include <cuda_bf16.h>
#include <cuda_fp16.h>
#include <math_constants.h>
#include <stdint.h>

#define BATCH 4
#define NTOK 4096
#define CIN 256
#define ADIM 128
#define MTOT (BATCH*NTOK)
#define NEG_SLOPE 0.2f
#define LOG2E 1.4426950408889634f

// ---------------- scratch ----------------
__device__ __nv_bfloat16 g_Xh[MTOT * CIN];
__device__ __nv_bfloat16 g_Xl[MTOT * CIN];
__device__ __nv_bfloat16 g_Qh[MTOT * ADIM];   // pre-scaled by log2(e)
__device__ __nv_bfloat16 g_Ql[MTOT * ADIM];
__device__ __nv_bfloat16 g_Kh[MTOT * ADIM];
__device__ __nv_bfloat16 g_Kl[MTOT * ADIM];
__device__ __half        g_V[MTOT * ADIM];
__device__ __nv_bfloat16 g_Oh[MTOT * ADIM];
__device__ __nv_bfloat16 g_Ol[MTOT * ADIM];
__device__ __nv_bfloat16 g_Wqh[CIN * ADIM], g_Wql[CIN * ADIM];
__device__ __nv_bfloat16 g_Wkh[CIN * ADIM], g_Wkl[CIN * ADIM];
__device__ __nv_bfloat16 g_Wvh[CIN * ADIM], g_Wvl[CIN * ADIM];
__device__ __nv_bfloat16 g_Woh[ADIM * CIN], g_Wol[ADIM * CIN];

__device__ __forceinline__ float lrelu(float x) { return x >= 0.0f ? x : NEG_SLOPE * x; }

// ---------------- helpers ----------------
__device__ __forceinline__ uint32_t smem_u32(const void* p) {
    uint32_t a;
    asm("{ .reg .u64 t; cvta.to.shared.u64 t, %1; cvt.u32.u64 %0, t; }" : "=r"(a) : "l"(p));
    return a;
}
__device__ __forceinline__ void cp16(uint32_t dst, const void* src) {
    asm volatile("cp.async.cg.shared.global [%0], [%1], 16;" :: "r"(dst), "l"(src));
}
__device__ __forceinline__ void cp_commit() { asm volatile("cp.async.commit_group;" ::: "memory"); }
__device__ __forceinline__ void cp_wait0() { asm volatile("cp.async.wait_group 0;" ::: "memory"); }
__device__ __forceinline__ void cp_wait1() { asm volatile("cp.async.wait_group 1;" ::: "memory"); }

__device__ __forceinline__ void ldsm4(uint32_t* r, uint32_t a) {
    asm volatile("ldmatrix.sync.aligned.m8n8.x4.shared.b16 {%0,%1,%2,%3}, [%4];"
        : "=r"(r[0]), "=r"(r[1]), "=r"(r[2]), "=r"(r[3]) : "r"(a));
}
__device__ __forceinline__ void ldsm4t(uint32_t* r, uint32_t a) {
    asm volatile("ldmatrix.sync.aligned.m8n8.x4.trans.shared.b16 {%0,%1,%2,%3}, [%4];"
        : "=r"(r[0]), "=r"(r[1]), "=r"(r[2]), "=r"(r[3]) : "r"(a));
}
__device__ __forceinline__ void mma_bf16(float* d, const uint32_t* a, const uint32_t* b) {
    asm volatile(
        "mma.sync.aligned.m16n8k16.row.col.f32.bf16.bf16.f32 "
        "{%0,%1,%2,%3}, {%4,%5,%6,%7}, {%8,%9}, {%0,%1,%2,%3};"
        : "+f"(d[0]), "+f"(d[1]), "+f"(d[2]), "+f"(d[3])
        : "r"(a[0]), "r"(a[1]), "r"(a[2]), "r"(a[3]), "r"(b[0]), "r"(b[1]));
}
__device__ __forceinline__ void mma_f16(float* d, const uint32_t* a, const uint32_t* b) {
    asm volatile(
        "mma.sync.aligned.m16n8k16.row.col.f32.f16.f16.f32 "
        "{%0,%1,%2,%3}, {%4,%5,%6,%7}, {%8,%9}, {%0,%1,%2,%3};"
        : "+f"(d[0]), "+f"(d[1]), "+f"(d[2]), "+f"(d[3])
        : "r"(a[0]), "r"(a[1]), "r"(a[2]), "r"(a[3]), "r"(b[0]), "r"(b[1]));
}
__device__ __forceinline__ uint32_t h2bits(__half2 v) { return *(uint32_t*)&v; }
__device__ __forceinline__ float ex2(float x) {
    float r; asm("ex2.approx.f32 %0, %1;" : "=f"(r) : "f"(x)); return r;
}

__device__ __forceinline__ void split2(float f0, float f1, __nv_bfloat162& h, __nv_bfloat162& l) {
    h = __floats2bfloat162_rn(f0, f1);
    l = __floats2bfloat162_rn(f0 - __bfloat162float(h.x), f1 - __bfloat162float(h.y));
}

// =====================================================================
// Convert kernels
// =====================================================================
__global__ __launch_bounds__(256)
void convx_kernel(const float* __restrict__ X) {
    int i = blockIdx.x * 256 + threadIdx.x;
    float4 v = ((const float4*)X)[i];
    __nv_bfloat162 h0, l0, h1, l1;
    split2(v.x, v.y, h0, l0);
    split2(v.z, v.w, h1, l1);
    ((__nv_bfloat162*)g_Xh)[2 * i] = h0;
    ((__nv_bfloat162*)g_Xh)[2 * i + 1] = h1;
    ((__nv_bfloat162*)g_Xl)[2 * i] = l0;
    ((__nv_bfloat162*)g_Xl)[2 * i + 1] = l1;
}

__global__ __launch_bounds__(256)
void convw_kernel(const float* __restrict__ Wq, const float* __restrict__ Wk,
                  const float* __restrict__ Wv, const float* __restrict__ Wo) {
    int j = blockIdx.x * 256 + threadIdx.x;
    int sel = j >> 13;
    int loc = j & 8191;
    const float* src = (sel == 0) ? Wq : (sel == 1) ? Wk : (sel == 2) ? Wv : Wo;
    __nv_bfloat16* dh = (sel == 0) ? g_Wqh : (sel == 1) ? g_Wkh : (sel == 2) ? g_Wvh : g_Woh;
    __nv_bfloat16* dl = (sel == 0) ? g_Wql : (sel == 1) ? g_Wkl : (sel == 2) ? g_Wvl : g_Wol;
    float4 v = ((const float4*)src)[loc];
    __nv_bfloat162 h0, l0, h1, l1;
    split2(v.x, v.y, h0, l0);
    split2(v.z, v.w, h1, l1);
    ((__nv_bfloat162*)dh)[2 * loc] = h0;
    ((__nv_bfloat162*)dh)[2 * loc + 1] = h1;
    ((__nv_bfloat162*)dl)[2 * loc] = l0;
    ((__nv_bfloat162*)dl)[2 * loc + 1] = l1;
}

// =====================================================================
// Kernel 1: QKV projection via mma.sync, 3xBF16 split.
// grid (128, 3), 256 threads. Q scaled by log2(e); V emitted as single fp16.
// =====================================================================
#define QKV2_XH 0
#define QKV2_XL 16384
#define QKV2_WH 32768
#define QKV2_WL 49152
#define QKV2_SMEM 65536

__global__ __launch_bounds__(256)
void qkv2_kernel() {
    extern __shared__ char smc[];
    const uint32_t sb = smem_u32(smc);
    const int tid = threadIdx.x;
    const int w = tid >> 5;
    const int lane = tid & 31;
    const int row0 = blockIdx.x * 128;

    const __nv_bfloat16 *WH, *WL;
    if (blockIdx.y == 0)      { WH = g_Wqh; WL = g_Wql; }
    else if (blockIdx.y == 1) { WH = g_Wkh; WL = g_Wkl; }
    else                      { WH = g_Wvh; WL = g_Wvl; }

    const int rowa = 16 * w + (lane & 15);
    const int ca = lane >> 4, swa = rowa & 7;
    const int rowv = (lane & 7) + (lane & 8);
    const int cv = (lane >> 4) & 1, swv = rowv & 7;

    float oacc[16][4];
    #pragma unroll
    for (int nb = 0; nb < 16; nb++)
        #pragma unroll
        for (int i = 0; i < 4; i++) oacc[nb][i] = 0.0f;

    #pragma unroll 1
    for (int kc = 0; kc < 4; kc++) {
        #pragma unroll
        for (int i = 0; i < 4; i++) {
            int lin = tid + i * 256;
            int r = lin >> 3, c = lin & 7;
            uint32_t off = (uint32_t)(r * 128 + ((c ^ (r & 7)) << 4));
            size_t g = (size_t)(row0 + r) * CIN + kc * 64 + c * 8;
            cp16(sb + QKV2_XH + off, g_Xh + g);
            cp16(sb + QKV2_XL + off, g_Xl + g);
        }
        #pragma unroll
        for (int i = 0; i < 4; i++) {
            int lin = tid + i * 256;
            int r = lin >> 4, c = lin & 15;
            uint32_t off = (uint32_t)(r * 256 + ((c ^ (r & 7)) << 4));
            size_t g = (size_t)(kc * 64 + r) * ADIM + c * 8;
            cp16(sb + QKV2_WH + off, WH + g);
            cp16(sb + QKV2_WL + off, WL + g);
        }
        cp_commit(); cp_wait0();
        __syncthreads();
        #pragma unroll
        for (int ks = 0; ks < 4; ks++) {
            uint32_t ah[4], al[4];
            uint32_t ach = (uint32_t)(((2 * ks + ca) ^ swa) << 4);
            ldsm4(ah, sb + QKV2_XH + rowa * 128 + ach);
            ldsm4(al, sb + QKV2_XL + rowa * 128 + ach);
            #pragma unroll
            for (int jp = 0; jp < 8; jp++) {
                uint32_t bh[4], bl[4];
                uint32_t boff = (uint32_t)((16 * ks + rowv) * 256 + (((2 * jp + cv) ^ swv) << 4));
                ldsm4t(bh, sb + QKV2_WH + boff);
                ldsm4t(bl, sb + QKV2_WL + boff);
                mma_bf16(oacc[2 * jp],     ah, bh); mma_bf16(oacc[2 * jp + 1], ah, bh + 2);
                mma_bf16(oacc[2 * jp],     ah, bl); mma_bf16(oacc[2 * jp + 1], ah, bl + 2);
                mma_bf16(oacc[2 * jp],     al, bh); mma_bf16(oacc[2 * jp + 1], al, bh + 2);
            }
        }
        __syncthreads();
    }

    const int r0 = row0 + 16 * w + (lane >> 2);
    const int cb2 = 2 * (lane & 3);
    if (blockIdx.y == 2) {
        #pragma unroll
        for (int nb = 0; nb < 16; nb++) {
            int c = nb * 8 + cb2;
            *(__half2*)&g_V[(size_t)r0 * ADIM + c] =
                __floats2half2_rn(lrelu(oacc[nb][0]), lrelu(oacc[nb][1]));
            *(__half2*)&g_V[(size_t)(r0 + 8) * ADIM + c] =
                __floats2half2_rn(lrelu(oacc[nb][2]), lrelu(oacc[nb][3]));
        }
    } else {
        __nv_bfloat16* OH = (blockIdx.y == 0) ? g_Qh : g_Kh;
        __nv_bfloat16* OL = (blockIdx.y == 0) ? g_Ql : g_Kl;
        const float sc = (blockIdx.y == 0) ? LOG2E : 1.0f;
        #pragma unroll
        for (int nb = 0; nb < 16; nb++) {
            int c = nb * 8 + cb2;
            __nv_bfloat162 h01, l01, h23, l23;
            split2(lrelu(oacc[nb][0]) * sc, lrelu(oacc[nb][1]) * sc, h01, l01);
            split2(lrelu(oacc[nb][2]) * sc, lrelu(oacc[nb][3]) * sc, h23, l23);
            *(__nv_bfloat162*)&OH[(size_t)r0 * ADIM + c] = h01;
            *(__nv_bfloat162*)&OL[(size_t)r0 * ADIM + c] = l01;
            *(__nv_bfloat162*)&OH[(size_t)(r0 + 8) * ADIM + c] = h23;
            *(__nv_bfloat162*)&OL[(size_t)(r0 + 8) * ADIM + c] = l23;
        }
    }
}

// =====================================================================
// Kernel 2: flash attention, software-pipelined. grid (32,4), 256 threads.
// S: 3-pass bf16 (log2 domain). PV: 1-pass fp16.
// Schedule: softmax(t) -> S-MMA(t+1) -> loads(t+2) -> PV(t).
// smem: Qh 32K | Ql 32K | 3 x {Kh 16K | Kl 16K | V 16K} = 208K
// =====================================================================
#define SQH 0
#define SQL 32768
#define SKV 65536
#define KVBUF 49152
#define ATTN_SMEM (65536 + 3*KVBUF)

__device__ __forceinline__ void load_kv(uint32_t dst, const __nv_bfloat16* kh,
                                        const __nv_bfloat16* kl, const __half* v, int tid) {
    #pragma unroll
    for (int i = 0; i < 4; i++) {
        int lin = tid + i * 256;
        int r = lin >> 4, c = lin & 15;
        uint32_t off = (uint32_t)(r * 256 + ((c ^ (r & 7)) << 4));
        size_t g = (size_t)r * ADIM + c * 8;
        cp16(dst + off, kh + g);
        cp16(dst + 16384 + off, kl + g);
        cp16(dst + 32768 + off, v + g);
    }
}

__global__ __launch_bounds__(256, 1)
void attn_kernel() {
    extern __shared__ char smc[];
    const uint32_t sb = smem_u32(smc);
    const int tid = threadIdx.x;
    const int w = tid >> 5;
    const int lane = tid & 31;
    const int b = blockIdx.y;
    const int q0 = blockIdx.x * 128;

    const int rowa = 16 * w + (lane & 15);
    const uint32_t qro = (uint32_t)rowa * 256;
    const int ca = lane >> 4;
    const int swa = rowa & 7;
    const int rowb = (lane & 7) + ((lane & 16) >> 1);
    const int cb = (lane >> 3) & 1;
    const int swb = rowb & 7;
    const int rowv = (lane & 7) + (lane & 8);
    const int cv = (lane >> 4) & 1;
    const int swv = rowv & 7;

    // ---- prologue: load Q + tile0 (group 0), tile1 (group 1) ----
    {
        const __nv_bfloat16* qh = g_Qh + (size_t)(b * NTOK + q0) * ADIM;
        const __nv_bfloat16* ql = g_Ql + (size_t)(b * NTOK + q0) * ADIM;
        #pragma unroll
        for (int i = 0; i < 8; i++) {
            int lin = tid + i * 256;
            int r = lin >> 4, c = lin & 15;
            uint32_t off = (uint32_t)(r * 256 + ((c ^ (r & 7)) << 4));
            size_t g = (size_t)r * ADIM + c * 8;
            cp16(sb + SQH + off, qh + g);
            cp16(sb + SQL + off, ql + g);
        }
    }
    const __nv_bfloat16* KHb = g_Kh + (size_t)b * NTOK * ADIM;
    const __nv_bfloat16* KLb = g_Kl + (size_t)b * NTOK * ADIM;
    const __half* Vb = g_V + (size_t)b * NTOK * ADIM;
    load_kv(sb + SKV, KHb, KLb, Vb, tid);
    cp_commit();                                           // group: Q + tile0
    load_kv(sb + SKV + KVBUF, KHb + 64 * ADIM, KLb + 64 * ADIM, Vb + 64 * ADIM, tid);
    cp_commit();                                           // group: tile1
    cp_wait1();                                            // Q + tile0 ready
    __syncthreads();

    float oacc[16][4];
    #pragma unroll
    for (int nb = 0; nb < 16; nb++)
        #pragma unroll
        for (int i = 0; i < 4; i++) oacc[nb][i] = 0.0f;
    float m0 = -CUDART_INF_F, m8 = -CUDART_INF_F, l0 = 0.0f, l8 = 0.0f;

    float sacc[8][4];

    // ---- S(0) ----
    #pragma unroll
    for (int nb = 0; nb < 8; nb++)
        #pragma unroll
        for (int i = 0; i < 4; i++) sacc[nb][i] = 0.0f;
    {
        const uint32_t KB = sb + SKV;
        #pragma unroll
        for (int ks = 0; ks < 8; ks++) {
            uint32_t aqh[4], aql[4];
            uint32_t ach = (uint32_t)(((2 * ks + ca) ^ swa) << 4);
            ldsm4(aqh, sb + SQH + qro + ach);
            ldsm4(aql, sb + SQL + qro + ach);
            uint32_t bch = (uint32_t)(((2 * ks + cb) ^ swb) << 4);
            #pragma unroll
            for (int jp = 0; jp < 4; jp++) {
                uint32_t bh[4], bl[4];
                uint32_t boff = (uint32_t)((16 * jp + rowb) * 256) + bch;
                ldsm4(bh, KB + boff);
                ldsm4(bl, KB + 16384u + boff);
                mma_bf16(sacc[2 * jp],     aqh, bh);
                mma_bf16(sacc[2 * jp + 1], aqh, bh + 2);
                mma_bf16(sacc[2 * jp],     aqh, bl);
                mma_bf16(sacc[2 * jp + 1], aqh, bl + 2);
                mma_bf16(sacc[2 * jp],     aql, bh);
                mma_bf16(sacc[2 * jp + 1], aql, bh + 2);
            }
        }
    }

    #pragma unroll 1
    for (int t = 0; t < 64; t++) {
        // ---- 1. softmax(t) (registers only) ----
        float rm0 = sacc[0][0], rm8 = sacc[0][2];
        #pragma unroll
        for (int nb = 0; nb < 8; nb++) {
            rm0 = fmaxf(rm0, fmaxf(sacc[nb][0], sacc[nb][1]));
            rm8 = fmaxf(rm8, fmaxf(sacc[nb][2], sacc[nb][3]));
        }
        rm0 = fmaxf(rm0, __shfl_xor_sync(0xffffffffu, rm0, 1));
        rm0 = fmaxf(rm0, __shfl_xor_sync(0xffffffffu, rm0, 2));
        rm8 = fmaxf(rm8, __shfl_xor_sync(0xffffffffu, rm8, 1));
        rm8 = fmaxf(rm8, __shfl_xor_sync(0xffffffffu, rm8, 2));
        float mn0 = fmaxf(m0, rm0), mn8 = fmaxf(m8, rm8);
        float sc0 = ex2(m0 - mn0), sc8 = ex2(m8 - mn8);
        m0 = mn0; m8 = mn8;

        uint32_t ph[8][2];
        float ls0 = 0.0f, ls8 = 0.0f;
        #pragma unroll
        for (int nb = 0; nb < 8; nb++) {
            float p0 = ex2(sacc[nb][0] - mn0);
            float p1 = ex2(sacc[nb][1] - mn0);
            float p2 = ex2(sacc[nb][2] - mn8);
            float p3 = ex2(sacc[nb][3] - mn8);
            ls0 += p0 + p1; ls8 += p2 + p3;
            ph[nb][0] = h2bits(__floats2half2_rn(p0, p1));
            ph[nb][1] = h2bits(__floats2half2_rn(p2, p3));
        }
        l0 = l0 * sc0 + ls0;
        l8 = l8 * sc8 + ls8;
        if (sc0 < 1.0f) {
            #pragma unroll
            for (int nb = 0; nb < 16; nb++) { oacc[nb][0] *= sc0; oacc[nb][1] *= sc0; }
        }
        if (sc8 < 1.0f) {
            #pragma unroll
            for (int nb = 0; nb < 16; nb++) { oacc[nb][2] *= sc8; oacc[nb][3] *= sc8; }
        }

        // ---- 2. wait tile t+1 loaded; sync (also fences buffer reuse) ----
        if (t < 63) cp_wait0();
        __syncthreads();

        // ---- 3. S(t+1) into sacc (K from buffer (t+1)%3) ----
        if (t < 63) {
            #pragma unroll
            for (int nb = 0; nb < 8; nb++)
                #pragma unroll
                for (int i = 0; i < 4; i++) sacc[nb][i] = 0.0f;
            const uint32_t KB = sb + SKV + (uint32_t)((t + 1) % 3) * (uint32_t)KVBUF;
            #pragma unroll
            for (int ks = 0; ks < 8; ks++) {
                uint32_t aqh[4], aql[4];
                uint32_t ach = (uint32_t)(((2 * ks + ca) ^ swa) << 4);
                ldsm4(aqh, sb + SQH + qro + ach);
                ldsm4(aql, sb + SQL + qro + ach);
                uint32_t bch = (uint32_t)(((2 * ks + cb) ^ swb) << 4);
                #pragma unroll
                for (int jp = 0; jp < 4; jp++) {
                    uint32_t bh[4], bl[4];
                    uint32_t boff = (uint32_t)((16 * jp + rowb) * 256) + bch;
                    ldsm4(bh, KB + boff);
                    ldsm4(bl, KB + 16384u + boff);
                    mma_bf16(sacc[2 * jp],     aqh, bh);
                    mma_bf16(sacc[2 * jp + 1], aqh, bh + 2);
                    mma_bf16(sacc[2 * jp],     aqh, bl);
                    mma_bf16(sacc[2 * jp + 1], aqh, bl + 2);
                    mma_bf16(sacc[2 * jp],     aql, bh);
                    mma_bf16(sacc[2 * jp + 1], aql, bh + 2);
                }
            }
        }

        // ---- 4. issue loads for tile t+2 into buffer (t+2)%3 ----
        if (t < 62) {
            size_t o = (size_t)(t + 2) * 64 * ADIM;
            load_kv(sb + SKV + (uint32_t)((t + 2) % 3) * (uint32_t)KVBUF,
                    KHb + o, KLb + o, Vb + o, tid);
            cp_commit();
        }

        // ---- 5. PV(t): O += P*V (V from buffer t%3) ----
        const uint32_t VB = sb + SKV + (uint32_t)(t % 3) * (uint32_t)KVBUF + 32768u;
        #pragma unroll
        for (int ks = 0; ks < 4; ks++) {
            uint32_t ah[4] = { ph[2 * ks][0], ph[2 * ks][1], ph[2 * ks + 1][0], ph[2 * ks + 1][1] };
            uint32_t vro = (uint32_t)((16 * ks + rowv) * 256);
            #pragma unroll
            for (int jp = 0; jp < 8; jp++) {
                uint32_t bh[4];
                uint32_t voff = vro + (uint32_t)(((2 * jp + cv) ^ swv) << 4);
                ldsm4t(bh, VB + voff);
                mma_f16(oacc[2 * jp],     ah, bh);
                mma_f16(oacc[2 * jp + 1], ah, bh + 2);
            }
        }
    }

    // ---- epilogue: normalize, split to bf16 hi/lo ----
    l0 += __shfl_xor_sync(0xffffffffu, l0, 1);
    l0 += __shfl_xor_sync(0xffffffffu, l0, 2);
    l8 += __shfl_xor_sync(0xffffffffu, l8, 1);
    l8 += __shfl_xor_sync(0xffffffffu, l8, 2);
    float inv0 = 1.0f / l0, inv8 = 1.0f / l8;
    size_t r0 = (size_t)b * NTOK + q0 + 16 * w + (lane >> 2);
    int cb2 = 2 * (lane & 3);
    #pragma unroll
    for (int nb = 0; nb < 16; nb++) {
        int c = nb * 8 + cb2;
        __nv_bfloat162 h01, l01, h23, l23;
        split2(oacc[nb][0] * inv0, oacc[nb][1] * inv0, h01, l01);
        split2(oacc[nb][2] * inv8, oacc[nb][3] * inv8, h23, l23);
        *(__nv_bfloat162*)&g_Oh[r0 * ADIM + c] = h01;
        *(__nv_bfloat162*)&g_Ol[r0 * ADIM + c] = l01;
        *(__nv_bfloat162*)&g_Oh[(r0 + 8) * ADIM + c] = h23;
        *(__nv_bfloat162*)&g_Ol[(r0 + 8) * ADIM + c] = l23;
    }
}

// =====================================================================
// Kernel 3: Y = O @ Wo * tanh(relu(1+wg)) via mma.sync, 3xBF16 split.
// grid (128, 2), 256 threads.
// =====================================================================
#define OUT2_AH 0
#define OUT2_AL 16384
#define OUT2_WH 32768
#define OUT2_WL 49152
#define OUT2_SMEM 65536

__global__ __launch_bounds__(256)
void out2_kernel(const float* __restrict__ wgm, float* __restrict__ Y) {
    extern __shared__ char smc[];
    const uint32_t sb = smem_u32(smc);
    const int tid = threadIdx.x;
    const int w = tid >> 5;
    const int lane = tid & 31;
    const int row0 = blockIdx.x * 128;
    const int col0 = blockIdx.y * 128;

    const int rowa = 16 * w + (lane & 15);
    const int ca = lane >> 4, swa = rowa & 7;
    const int rowv = (lane & 7) + (lane & 8);
    const int cv = (lane >> 4) & 1, swv = rowv & 7;

    float oacc[16][4];
    #pragma unroll
    for (int nb = 0; nb < 16; nb++)
        #pragma unroll
        for (int i = 0; i < 4; i++) oacc[nb][i] = 0.0f;

    #pragma unroll 1
    for (int kc = 0; kc < 2; kc++) {
        #pragma unroll
        for (int i = 0; i < 4; i++) {
            int lin = tid + i * 256;
            int r = lin >> 3, c = lin & 7;
            uint32_t off = (uint32_t)(r * 128 + ((c ^ (r & 7)) << 4));
            size_t g = (size_t)(row0 + r) * ADIM + kc * 64 + c * 8;
            cp16(sb + OUT2_AH + off, g_Oh + g);
            cp16(sb + OUT2_AL + off, g_Ol + g);
        }
        #pragma unroll
        for (int i = 0; i < 4; i++) {
            int lin = tid + i * 256;
            int r = lin >> 4, c = lin & 15;
            uint32_t off = (uint32_t)(r * 256 + ((c ^ (r & 7)) << 4));
            size_t g = (size_t)(kc * 64 + r) * CIN + col0 + c * 8;
            cp16(sb + OUT2_WH + off, g_Woh + g);
            cp16(sb + OUT2_WL + off, g_Wol + g);
        }
        cp_commit(); cp_wait0();
        __syncthreads();
        #pragma unroll
        for (int ks = 0; ks < 4; ks++) {
            uint32_t ah[4], al[4];
            uint32_t ach = (uint32_t)(((2 * ks + ca) ^ swa) << 4);
            ldsm4(ah, sb + OUT2_AH + rowa * 128 + ach);
            ldsm4(al, sb + OUT2_AL + rowa * 128 + ach);
            #pragma unroll
            for (int jp = 0; jp < 8; jp++) {
                uint32_t bh[4], bl[4];
                uint32_t boff = (uint32_t)((16 * ks + rowv) * 256 + (((2 * jp + cv) ^ swv) << 4));
                ldsm4t(bh, sb + OUT2_WH + boff);
                ldsm4t(bl, sb + OUT2_WL + boff);
                mma_bf16(oacc[2 * jp],     ah, bh); mma_bf16(oacc[2 * jp + 1], ah, bh + 2);
                mma_bf16(oacc[2 * jp],     ah, bl); mma_bf16(oacc[2 * jp + 1], ah, bl + 2);
                mma_bf16(oacc[2 * jp],     al, bh); mma_bf16(oacc[2 * jp + 1], al, bh + 2);
            }
        }
        __syncthreads();
    }

    const int r0 = row0 + 16 * w + (lane >> 2);
    const int cb2 = 2 * (lane & 3);
    #pragma unroll
    for (int nb = 0; nb < 16; nb++) {
        int c = col0 + nb * 8 + cb2;
        float g0 = tanhf(fmaxf(1.0f + wgm[c], 0.0f));
        float g1 = tanhf(fmaxf(1.0f + wgm[c + 1], 0.0f));
        *(float2*)&Y[(size_t)r0 * CIN + c] =
            make_float2(oacc[nb][0] * g0, oacc[nb][1] * g1);
        *(float2*)&Y[(size_t)(r0 + 8) * CIN + c] =
            make_float2(oacc[nb][2] * g0, oacc[nb][3] * g1);
    }
}

// =====================================================================
extern "C" void kernel_launch(void* const* d_in, const int* in_sizes, int n_in,
                              void* d_out, int out_size) {
    const float* x  = (const float*)d_in[0];
    const float* Wq = (const float*)d_in[1];
    const float* Wk = (const float*)d_in[2];
    const float* Wv = (const float*)d_in[3];
    const float* Wo = (const float*)d_in[4];
    const float* wg = (const float*)d_in[5];
    float* y = (float*)d_out;

    static bool attrs_set = []() {
        cudaFuncSetAttribute(qkv2_kernel, cudaFuncAttributeMaxDynamicSharedMemorySize, QKV2_SMEM);
        cudaFuncSetAttribute(attn_kernel, cudaFuncAttributeMaxDynamicSharedMemorySize, ATTN_SMEM);
        cudaFuncSetAttribute(out2_kernel, cudaFuncAttributeMaxDynamicSharedMemorySize, OUT2_SMEM);
        return true;
    }();
    (void)attrs_set;

    convx_kernel<<<4096, 256>>>(x);
    convw_kernel<<<128, 256>>>(Wq, Wk, Wv, Wo);
    qkv2_kernel<<<dim3(128, 3), 256, QKV2_SMEM>>>();
    attn_kernel<<<dim3(NTOK / 128, BATCH), 256, ATTN_SMEM>>>();
    out2_kernel<<<dim3(128, 2), 256, OUT2_SMEM>>>(wg, y);
}

// round 11
// speedup vs baseline: 1.4147x; 1.0340x over previous
#include <cuda_runtime.h>
#include <cuda_bf16.h>
#include <cuda_fp16.h>
#include <math_constants.h>
#include <stdint.h>

#define BATCH 4
#define NTOK 4096
#define CIN 256
#define ADIM 128
#define MTOT (BATCH*NTOK)
#define NEG_SLOPE 0.2f
#define LOG2E 1.4426950408889634f

// ---------------- scratch ----------------
__device__ __nv_bfloat16 g_Xh[MTOT * CIN];
__device__ __nv_bfloat16 g_Xl[MTOT * CIN];
__device__ __nv_bfloat16 g_Qh[MTOT * ADIM];   // pre-scaled by log2(e)
__device__ __nv_bfloat16 g_Ql[MTOT * ADIM];
__device__ __nv_bfloat16 g_Kh[MTOT * ADIM];
__device__ __nv_bfloat16 g_Kl[MTOT * ADIM];
__device__ __half        g_V[MTOT * ADIM];
__device__ __nv_bfloat16 g_Oh[MTOT * ADIM];
__device__ __nv_bfloat16 g_Ol[MTOT * ADIM];
__device__ __nv_bfloat16 g_Wqh[CIN * ADIM], g_Wql[CIN * ADIM];
__device__ __nv_bfloat16 g_Wkh[CIN * ADIM], g_Wkl[CIN * ADIM];
__device__ __nv_bfloat16 g_Wvh[CIN * ADIM], g_Wvl[CIN * ADIM];
__device__ __nv_bfloat16 g_Woh[ADIM * CIN], g_Wol[ADIM * CIN];

__device__ __forceinline__ float lrelu(float x) { return x >= 0.0f ? x : NEG_SLOPE * x; }

// ---------------- helpers ----------------
__device__ __forceinline__ uint32_t smem_u32(const void* p) {
    uint32_t a;
    asm("{ .reg .u64 t; cvta.to.shared.u64 t, %1; cvt.u32.u64 %0, t; }" : "=r"(a) : "l"(p));
    return a;
}
__device__ __forceinline__ void cp16(uint32_t dst, const void* src) {
    asm volatile("cp.async.cg.shared.global [%0], [%1], 16;" :: "r"(dst), "l"(src));
}
__device__ __forceinline__ void cp_commit() { asm volatile("cp.async.commit_group;" ::: "memory"); }
__device__ __forceinline__ void cp_wait0() { asm volatile("cp.async.wait_group 0;" ::: "memory"); }
__device__ __forceinline__ void cp_wait1() { asm volatile("cp.async.wait_group 1;" ::: "memory"); }

__device__ __forceinline__ void ldsm4(uint32_t* r, uint32_t a) {
    asm volatile("ldmatrix.sync.aligned.m8n8.x4.shared.b16 {%0,%1,%2,%3}, [%4];"
        : "=r"(r[0]), "=r"(r[1]), "=r"(r[2]), "=r"(r[3]) : "r"(a));
}
__device__ __forceinline__ void ldsm4t(uint32_t* r, uint32_t a) {
    asm volatile("ldmatrix.sync.aligned.m8n8.x4.trans.shared.b16 {%0,%1,%2,%3}, [%4];"
        : "=r"(r[0]), "=r"(r[1]), "=r"(r[2]), "=r"(r[3]) : "r"(a));
}
__device__ __forceinline__ void mma_bf16(float* d, const uint32_t* a, const uint32_t* b) {
    asm volatile(
        "mma.sync.aligned.m16n8k16.row.col.f32.bf16.bf16.f32 "
        "{%0,%1,%2,%3}, {%4,%5,%6,%7}, {%8,%9}, {%0,%1,%2,%3};"
        : "+f"(d[0]), "+f"(d[1]), "+f"(d[2]), "+f"(d[3])
        : "r"(a[0]), "r"(a[1]), "r"(a[2]), "r"(a[3]), "r"(b[0]), "r"(b[1]));
}
__device__ __forceinline__ void mma_f16(float* d, const uint32_t* a, const uint32_t* b) {
    asm volatile(
        "mma.sync.aligned.m16n8k16.row.col.f32.f16.f16.f32 "
        "{%0,%1,%2,%3}, {%4,%5,%6,%7}, {%8,%9}, {%0,%1,%2,%3};"
        : "+f"(d[0]), "+f"(d[1]), "+f"(d[2]), "+f"(d[3])
        : "r"(a[0]), "r"(a[1]), "r"(a[2]), "r"(a[3]), "r"(b[0]), "r"(b[1]));
}
__device__ __forceinline__ uint32_t h2bits(__half2 v) { return *(uint32_t*)&v; }
__device__ __forceinline__ float ex2(float x) {
    float r; asm("ex2.approx.f32 %0, %1;" : "=f"(r) : "f"(x)); return r;
}

__device__ __forceinline__ void split2(float f0, float f1, __nv_bfloat162& h, __nv_bfloat162& l) {
    h = __floats2bfloat162_rn(f0, f1);
    l = __floats2bfloat162_rn(f0 - __bfloat162float(h.x), f1 - __bfloat162float(h.y));
}

// =====================================================================
// Convert kernels
// =====================================================================
__global__ __launch_bounds__(256)
void convx_kernel(const float* __restrict__ X) {
    int i = blockIdx.x * 256 + threadIdx.x;
    float4 v = ((const float4*)X)[i];
    __nv_bfloat162 h0, l0, h1, l1;
    split2(v.x, v.y, h0, l0);
    split2(v.z, v.w, h1, l1);
    ((__nv_bfloat162*)g_Xh)[2 * i] = h0;
    ((__nv_bfloat162*)g_Xh)[2 * i + 1] = h1;
    ((__nv_bfloat162*)g_Xl)[2 * i] = l0;
    ((__nv_bfloat162*)g_Xl)[2 * i + 1] = l1;
}

__global__ __launch_bounds__(256)
void convw_kernel(const float* __restrict__ Wq, const float* __restrict__ Wk,
                  const float* __restrict__ Wv, const float* __restrict__ Wo) {
    int j = blockIdx.x * 256 + threadIdx.x;
    int sel = j >> 13;
    int loc = j & 8191;
    const float* src = (sel == 0) ? Wq : (sel == 1) ? Wk : (sel == 2) ? Wv : Wo;
    __nv_bfloat16* dh = (sel == 0) ? g_Wqh : (sel == 1) ? g_Wkh : (sel == 2) ? g_Wvh : g_Woh;
    __nv_bfloat16* dl = (sel == 0) ? g_Wql : (sel == 1) ? g_Wkl : (sel == 2) ? g_Wvl : g_Wol;
    float4 v = ((const float4*)src)[loc];
    __nv_bfloat162 h0, l0, h1, l1;
    split2(v.x, v.y, h0, l0);
    split2(v.z, v.w, h1, l1);
    ((__nv_bfloat162*)dh)[2 * loc] = h0;
    ((__nv_bfloat162*)dh)[2 * loc + 1] = h1;
    ((__nv_bfloat162*)dl)[2 * loc] = l0;
    ((__nv_bfloat162*)dl)[2 * loc + 1] = l1;
}

// =====================================================================
// Kernel 1: QKV projection via mma.sync, 3xBF16 split.
// grid (128, 3), 256 threads. Q scaled by log2(e); V emitted as single fp16.
// =====================================================================
#define QKV2_XH 0
#define QKV2_XL 16384
#define QKV2_WH 32768
#define QKV2_WL 49152
#define QKV2_SMEM 65536

__global__ __launch_bounds__(256)
void qkv2_kernel() {
    extern __shared__ char smc[];
    const uint32_t sb = smem_u32(smc);
    const int tid = threadIdx.x;
    const int w = tid >> 5;
    const int lane = tid & 31;
    const int row0 = blockIdx.x * 128;

    const __nv_bfloat16 *WH, *WL;
    if (blockIdx.y == 0)      { WH = g_Wqh; WL = g_Wql; }
    else if (blockIdx.y == 1) { WH = g_Wkh; WL = g_Wkl; }
    else                      { WH = g_Wvh; WL = g_Wvl; }

    const int rowa = 16 * w + (lane & 15);
    const int ca = lane >> 4, swa = rowa & 7;
    const int rowv = (lane & 7) + (lane & 8);
    const int cv = (lane >> 4) & 1, swv = rowv & 7;

    float oacc[16][4];
    #pragma unroll
    for (int nb = 0; nb < 16; nb++)
        #pragma unroll
        for (int i = 0; i < 4; i++) oacc[nb][i] = 0.0f;

    #pragma unroll 1
    for (int kc = 0; kc < 4; kc++) {
        #pragma unroll
        for (int i = 0; i < 4; i++) {
            int lin = tid + i * 256;
            int r = lin >> 3, c = lin & 7;
            uint32_t off = (uint32_t)(r * 128 + ((c ^ (r & 7)) << 4));
            size_t g = (size_t)(row0 + r) * CIN + kc * 64 + c * 8;
            cp16(sb + QKV2_XH + off, g_Xh + g);
            cp16(sb + QKV2_XL + off, g_Xl + g);
        }
        #pragma unroll
        for (int i = 0; i < 4; i++) {
            int lin = tid + i * 256;
            int r = lin >> 4, c = lin & 15;
            uint32_t off = (uint32_t)(r * 256 + ((c ^ (r & 7)) << 4));
            size_t g = (size_t)(kc * 64 + r) * ADIM + c * 8;
            cp16(sb + QKV2_WH + off, WH + g);
            cp16(sb + QKV2_WL + off, WL + g);
        }
        cp_commit(); cp_wait0();
        __syncthreads();
        #pragma unroll
        for (int ks = 0; ks < 4; ks++) {
            uint32_t ah[4], al[4];
            uint32_t ach = (uint32_t)(((2 * ks + ca) ^ swa) << 4);
            ldsm4(ah, sb + QKV2_XH + rowa * 128 + ach);
            ldsm4(al, sb + QKV2_XL + rowa * 128 + ach);
            #pragma unroll
            for (int jp = 0; jp < 8; jp++) {
                uint32_t bh[4], bl[4];
                uint32_t boff = (uint32_t)((16 * ks + rowv) * 256 + (((2 * jp + cv) ^ swv) << 4));
                ldsm4t(bh, sb + QKV2_WH + boff);
                ldsm4t(bl, sb + QKV2_WL + boff);
                mma_bf16(oacc[2 * jp],     ah, bh); mma_bf16(oacc[2 * jp + 1], ah, bh + 2);
                mma_bf16(oacc[2 * jp],     ah, bl); mma_bf16(oacc[2 * jp + 1], ah, bl + 2);
                mma_bf16(oacc[2 * jp],     al, bh); mma_bf16(oacc[2 * jp + 1], al, bh + 2);
            }
        }
        __syncthreads();
    }

    const int r0 = row0 + 16 * w + (lane >> 2);
    const int cb2 = 2 * (lane & 3);
    if (blockIdx.y == 2) {
        #pragma unroll
        for (int nb = 0; nb < 16; nb++) {
            int c = nb * 8 + cb2;
            *(__half2*)&g_V[(size_t)r0 * ADIM + c] =
                __floats2half2_rn(lrelu(oacc[nb][0]), lrelu(oacc[nb][1]));
            *(__half2*)&g_V[(size_t)(r0 + 8) * ADIM + c] =
                __floats2half2_rn(lrelu(oacc[nb][2]), lrelu(oacc[nb][3]));
        }
    } else {
        __nv_bfloat16* OH = (blockIdx.y == 0) ? g_Qh : g_Kh;
        __nv_bfloat16* OL = (blockIdx.y == 0) ? g_Ql : g_Kl;
        const float sc = (blockIdx.y == 0) ? LOG2E : 1.0f;
        #pragma unroll
        for (int nb = 0; nb < 16; nb++) {
            int c = nb * 8 + cb2;
            __nv_bfloat162 h01, l01, h23, l23;
            split2(lrelu(oacc[nb][0]) * sc, lrelu(oacc[nb][1]) * sc, h01, l01);
            split2(lrelu(oacc[nb][2]) * sc, lrelu(oacc[nb][3]) * sc, h23, l23);
            *(__nv_bfloat162*)&OH[(size_t)r0 * ADIM + c] = h01;
            *(__nv_bfloat162*)&OL[(size_t)r0 * ADIM + c] = l01;
            *(__nv_bfloat162*)&OH[(size_t)(r0 + 8) * ADIM + c] = h23;
            *(__nv_bfloat162*)&OL[(size_t)(r0 + 8) * ADIM + c] = l23;
        }
    }
}

// =====================================================================
// Kernel 2: flash attention, software-pipelined with double sacc.
// grid (32,4), 256 threads.
// Per iter: wait -> sync -> S-MMA(t+1)->other sacc -> loads(t+2)
//           -> softmax(t) [overlaps S-MMA execution] -> PV(t).
// smem: Qh 32K | Ql 32K | 3 x {Kh 16K | Kl 16K | V 16K} = 208K
// =====================================================================
#define SQH 0
#define SQL 32768
#define SKV 65536
#define KVBUF 49152
#define ATTN_SMEM (65536 + 3*KVBUF)

__device__ __forceinline__ void load_kv(uint32_t dst, const __nv_bfloat16* kh,
                                        const __nv_bfloat16* kl, const __half* v, int tid) {
    #pragma unroll
    for (int i = 0; i < 4; i++) {
        int lin = tid + i * 256;
        int r = lin >> 4, c = lin & 15;
        uint32_t off = (uint32_t)(r * 256 + ((c ^ (r & 7)) << 4));
        size_t g = (size_t)r * ADIM + c * 8;
        cp16(dst + off, kh + g);
        cp16(dst + 16384 + off, kl + g);
        cp16(dst + 32768 + off, v + g);
    }
}

__global__ __launch_bounds__(256, 1)
void attn_kernel() {
    extern __shared__ char smc[];
    const uint32_t sb = smem_u32(smc);
    const int tid = threadIdx.x;
    const int w = tid >> 5;
    const int lane = tid & 31;
    const int b = blockIdx.y;
    const int q0 = blockIdx.x * 128;

    const int rowa = 16 * w + (lane & 15);
    const uint32_t qro = (uint32_t)rowa * 256;
    const int ca = lane >> 4;
    const int swa = rowa & 7;
    const int rowb = (lane & 7) + ((lane & 16) >> 1);
    const int cb = (lane >> 3) & 1;
    const int swb = rowb & 7;
    const int rowv = (lane & 7) + (lane & 8);
    const int cv = (lane >> 4) & 1;
    const int swv = rowv & 7;

    // ---- prologue ----
    {
        const __nv_bfloat16* qh = g_Qh + (size_t)(b * NTOK + q0) * ADIM;
        const __nv_bfloat16* ql = g_Ql + (size_t)(b * NTOK + q0) * ADIM;
        #pragma unroll
        for (int i = 0; i < 8; i++) {
            int lin = tid + i * 256;
            int r = lin >> 4, c = lin & 15;
            uint32_t off = (uint32_t)(r * 256 + ((c ^ (r & 7)) << 4));
            size_t g = (size_t)r * ADIM + c * 8;
            cp16(sb + SQH + off, qh + g);
            cp16(sb + SQL + off, ql + g);
        }
    }
    const __nv_bfloat16* KHb = g_Kh + (size_t)b * NTOK * ADIM;
    const __nv_bfloat16* KLb = g_Kl + (size_t)b * NTOK * ADIM;
    const __half* Vb = g_V + (size_t)b * NTOK * ADIM;
    load_kv(sb + SKV, KHb, KLb, Vb, tid);
    cp_commit();
    load_kv(sb + SKV + KVBUF, KHb + 64 * ADIM, KLb + 64 * ADIM, Vb + 64 * ADIM, tid);
    cp_commit();
    cp_wait1();
    __syncthreads();

    float oacc[16][4];
    #pragma unroll
    for (int nb = 0; nb < 16; nb++)
        #pragma unroll
        for (int i = 0; i < 4; i++) oacc[nb][i] = 0.0f;
    float m0 = -CUDART_INF_F, m8 = -CUDART_INF_F, l0 = 0.0f, l8 = 0.0f;

    float sA[8][4], sB[8][4];

    // S-MMA into a given accumulator from K buffer
    auto s_mma = [&](float (&sacc)[8][4], uint32_t KB) {
        #pragma unroll
        for (int nb = 0; nb < 8; nb++)
            #pragma unroll
            for (int i = 0; i < 4; i++) sacc[nb][i] = 0.0f;
        #pragma unroll
        for (int ks = 0; ks < 8; ks++) {
            uint32_t aqh[4], aql[4];
            uint32_t ach = (uint32_t)(((2 * ks + ca) ^ swa) << 4);
            ldsm4(aqh, sb + SQH + qro + ach);
            ldsm4(aql, sb + SQL + qro + ach);
            uint32_t bch = (uint32_t)(((2 * ks + cb) ^ swb) << 4);
            #pragma unroll
            for (int jp = 0; jp < 4; jp++) {
                uint32_t bh[4], bl[4];
                uint32_t boff = (uint32_t)((16 * jp + rowb) * 256) + bch;
                ldsm4(bh, KB + boff);
                ldsm4(bl, KB + 16384u + boff);
                mma_bf16(sacc[2 * jp],     aqh, bh);
                mma_bf16(sacc[2 * jp + 1], aqh, bh + 2);
                mma_bf16(sacc[2 * jp],     aqh, bl);
                mma_bf16(sacc[2 * jp + 1], aqh, bl + 2);
                mma_bf16(sacc[2 * jp],     aql, bh);
                mma_bf16(sacc[2 * jp + 1], aql, bh + 2);
            }
        }
    };

    // softmax on sacc (completed) then PV from VB
    auto softmax_pv = [&](float (&sacc)[8][4], uint32_t VB) {
        float rm0 = sacc[0][0], rm8 = sacc[0][2];
        #pragma unroll
        for (int nb = 0; nb < 8; nb++) {
            rm0 = fmaxf(rm0, fmaxf(sacc[nb][0], sacc[nb][1]));
            rm8 = fmaxf(rm8, fmaxf(sacc[nb][2], sacc[nb][3]));
        }
        rm0 = fmaxf(rm0, __shfl_xor_sync(0xffffffffu, rm0, 1));
        rm0 = fmaxf(rm0, __shfl_xor_sync(0xffffffffu, rm0, 2));
        rm8 = fmaxf(rm8, __shfl_xor_sync(0xffffffffu, rm8, 1));
        rm8 = fmaxf(rm8, __shfl_xor_sync(0xffffffffu, rm8, 2));
        float mn0 = fmaxf(m0, rm0), mn8 = fmaxf(m8, rm8);
        float sc0 = ex2(m0 - mn0), sc8 = ex2(m8 - mn8);
        m0 = mn0; m8 = mn8;

        uint32_t ph[8][2];
        float ls0 = 0.0f, ls8 = 0.0f;
        #pragma unroll
        for (int nb = 0; nb < 8; nb++) {
            float p0 = ex2(sacc[nb][0] - mn0);
            float p1 = ex2(sacc[nb][1] - mn0);
            float p2 = ex2(sacc[nb][2] - mn8);
            float p3 = ex2(sacc[nb][3] - mn8);
            ls0 += p0 + p1; ls8 += p2 + p3;
            ph[nb][0] = h2bits(__floats2half2_rn(p0, p1));
            ph[nb][1] = h2bits(__floats2half2_rn(p2, p3));
        }
        l0 = l0 * sc0 + ls0;
        l8 = l8 * sc8 + ls8;
        if (sc0 < 1.0f) {
            #pragma unroll
            for (int nb = 0; nb < 16; nb++) { oacc[nb][0] *= sc0; oacc[nb][1] *= sc0; }
        }
        if (sc8 < 1.0f) {
            #pragma unroll
            for (int nb = 0; nb < 16; nb++) { oacc[nb][2] *= sc8; oacc[nb][3] *= sc8; }
        }

        #pragma unroll
        for (int ks = 0; ks < 4; ks++) {
            uint32_t ah[4] = { ph[2 * ks][0], ph[2 * ks][1], ph[2 * ks + 1][0], ph[2 * ks + 1][1] };
            uint32_t vro = (uint32_t)((16 * ks + rowv) * 256);
            #pragma unroll
            for (int jp = 0; jp < 8; jp++) {
                uint32_t bh[4];
                uint32_t voff = vro + (uint32_t)(((2 * jp + cv) ^ swv) << 4);
                ldsm4t(bh, VB + voff);
                mma_f16(oacc[2 * jp],     ah, bh);
                mma_f16(oacc[2 * jp + 1], ah, bh + 2);
            }
        }
    };

    auto kbuf = [&](int i) { return sb + SKV + (uint32_t)(i % 3) * (uint32_t)KVBUF; };
    auto vbuf = [&](int i) { return sb + SKV + (uint32_t)(i % 3) * (uint32_t)KVBUF + 32768u; };

    // S(0) into sA
    s_mma(sA, kbuf(0));

    #pragma unroll 1
    for (int t = 0; t < 64; t += 2) {
        // even sub-iter: current = sA, next S -> sB
        if (t < 63) cp_wait0();
        __syncthreads();
        if (t < 63) s_mma(sB, kbuf(t + 1));
        if (t < 62) {
            size_t o = (size_t)(t + 2) * 64 * ADIM;
            load_kv(kbuf(t + 2), KHb + o, KLb + o, Vb + o, tid);
            cp_commit();
        }
        softmax_pv(sA, vbuf(t));

        // odd sub-iter: current = sB, next S -> sA
        const int u = t + 1;
        if (u < 63) cp_wait0();
        __syncthreads();
        if (u < 63) s_mma(sA, kbuf(u + 1));
        if (u < 62) {
            size_t o = (size_t)(u + 2) * 64 * ADIM;
            load_kv(kbuf(u + 2), KHb + o, KLb + o, Vb + o, tid);
            cp_commit();
        }
        softmax_pv(sB, vbuf(u));
    }

    // ---- epilogue: normalize, split to bf16 hi/lo ----
    l0 += __shfl_xor_sync(0xffffffffu, l0, 1);
    l0 += __shfl_xor_sync(0xffffffffu, l0, 2);
    l8 += __shfl_xor_sync(0xffffffffu, l8, 1);
    l8 += __shfl_xor_sync(0xffffffffu, l8, 2);
    float inv0 = 1.0f / l0, inv8 = 1.0f / l8;
    size_t r0 = (size_t)b * NTOK + q0 + 16 * w + (lane >> 2);
    int cb2 = 2 * (lane & 3);
    #pragma unroll
    for (int nb = 0; nb < 16; nb++) {
        int c = nb * 8 + cb2;
        __nv_bfloat162 h01, l01, h23, l23;
        split2(oacc[nb][0] * inv0, oacc[nb][1] * inv0, h01, l01);
        split2(oacc[nb][2] * inv8, oacc[nb][3] * inv8, h23, l23);
        *(__nv_bfloat162*)&g_Oh[r0 * ADIM + c] = h01;
        *(__nv_bfloat162*)&g_Ol[r0 * ADIM + c] = l01;
        *(__nv_bfloat162*)&g_Oh[(r0 + 8) * ADIM + c] = h23;
        *(__nv_bfloat162*)&g_Ol[(r0 + 8) * ADIM + c] = l23;
    }
}

// =====================================================================
// Kernel 3: Y = O @ Wo * tanh(relu(1+wg)) via mma.sync, 3xBF16 split.
// grid (128, 2), 256 threads.
// =====================================================================
#define OUT2_AH 0
#define OUT2_AL 16384
#define OUT2_WH 32768
#define OUT2_WL 49152
#define OUT2_SMEM 65536

__global__ __launch_bounds__(256)
void out2_kernel(const float* __restrict__ wgm, float* __restrict__ Y) {
    extern __shared__ char smc[];
    const uint32_t sb = smem_u32(smc);
    const int tid = threadIdx.x;
    const int w = tid >> 5;
    const int lane = tid & 31;
    const int row0 = blockIdx.x * 128;
    const int col0 = blockIdx.y * 128;

    const int rowa = 16 * w + (lane & 15);
    const int ca = lane >> 4, swa = rowa & 7;
    const int rowv = (lane & 7) + (lane & 8);
    const int cv = (lane >> 4) & 1, swv = rowv & 7;

    float oacc[16][4];
    #pragma unroll
    for (int nb = 0; nb < 16; nb++)
        #pragma unroll
        for (int i = 0; i < 4; i++) oacc[nb][i] = 0.0f;

    #pragma unroll 1
    for (int kc = 0; kc < 2; kc++) {
        #pragma unroll
        for (int i = 0; i < 4; i++) {
            int lin = tid + i * 256;
            int r = lin >> 3, c = lin & 7;
            uint32_t off = (uint32_t)(r * 128 + ((c ^ (r & 7)) << 4));
            size_t g = (size_t)(row0 + r) * ADIM + kc * 64 + c * 8;
            cp16(sb + OUT2_AH + off, g_Oh + g);
            cp16(sb + OUT2_AL + off, g_Ol + g);
        }
        #pragma unroll
        for (int i = 0; i < 4; i++) {
            int lin = tid + i * 256;
            int r = lin >> 4, c = lin & 15;
            uint32_t off = (uint32_t)(r * 256 + ((c ^ (r & 7)) << 4));
            size_t g = (size_t)(kc * 64 + r) * CIN + col0 + c * 8;
            cp16(sb + OUT2_WH + off, g_Woh + g);
            cp16(sb + OUT2_WL + off, g_Wol + g);
        }
        cp_commit(); cp_wait0();
        __syncthreads();
        #pragma unroll
        for (int ks = 0; ks < 4; ks++) {
            uint32_t ah[4], al[4];
            uint32_t ach = (uint32_t)(((2 * ks + ca) ^ swa) << 4);
            ldsm4(ah, sb + OUT2_AH + rowa * 128 + ach);
            ldsm4(al, sb + OUT2_AL + rowa * 128 + ach);
            #pragma unroll
            for (int jp = 0; jp < 8; jp++) {
                uint32_t bh[4], bl[4];
                uint32_t boff = (uint32_t)((16 * ks + rowv) * 256 + (((2 * jp + cv) ^ swv) << 4));
                ldsm4t(bh, sb + OUT2_WH + boff);
                ldsm4t(bl, sb + OUT2_WL + boff);
                mma_bf16(oacc[2 * jp],     ah, bh); mma_bf16(oacc[2 * jp + 1], ah, bh + 2);
                mma_bf16(oacc[2 * jp],     ah, bl); mma_bf16(oacc[2 * jp + 1], ah, bl + 2);
                mma_bf16(oacc[2 * jp],     al, bh); mma_bf16(oacc[2 * jp + 1], al, bh + 2);
            }
        }
        __syncthreads();
    }

    const int r0 = row0 + 16 * w + (lane >> 2);
    const int cb2 = 2 * (lane & 3);
    #pragma unroll
    for (int nb = 0; nb < 16; nb++) {
        int c = col0 + nb * 8 + cb2;
        float g0 = tanhf(fmaxf(1.0f + wgm[c], 0.0f));
        float g1 = tanhf(fmaxf(1.0f + wgm[c + 1], 0.0f));
        *(float2*)&Y[(size_t)r0 * CIN + c] =
            make_float2(oacc[nb][0] * g0, oacc[nb][1] * g1);
        *(float2*)&Y[(size_t)(r0 + 8) * CIN + c] =
            make_float2(oacc[nb][2] * g0, oacc[nb][3] * g1);
    }
}

// =====================================================================
extern "C" void kernel_launch(void* const* d_in, const int* in_sizes, int n_in,
                              void* d_out, int out_size) {
    const float* x  = (const float*)d_in[0];
    const float* Wq = (const float*)d_in[1];
    const float* Wk = (const float*)d_in[2];
    const float* Wv = (const float*)d_in[3];
    const float* Wo = (const float*)d_in[4];
    const float* wg = (const float*)d_in[5];
    float* y = (float*)d_out;

    static bool attrs_set = []() {
        cudaFuncSetAttribute(qkv2_kernel, cudaFuncAttributeMaxDynamicSharedMemorySize, QKV2_SMEM);
        cudaFuncSetAttribute(attn_kernel, cudaFuncAttributeMaxDynamicSharedMemorySize, ATTN_SMEM);
        cudaFuncSetAttribute(out2_kernel, cudaFuncAttributeMaxDynamicSharedMemorySize, OUT2_SMEM);
        return true;
    }();
    (void)attrs_set;

    convx_kernel<<<4096, 256>>>(x);
    convw_kernel<<<128, 256>>>(Wq, Wk, Wv, Wo);
    qkv2_kernel<<<dim3(128, 3), 256, QKV2_SMEM>>>();
    attn_kernel<<<dim3(NTOK / 128, BATCH), 256, ATTN_SMEM>>>();
    out2_kernel<<<dim3(128, 2), 256, OUT2_SMEM>>>(wg, y);
}

// round 12
// speedup vs baseline: 1.4273x; 1.0089x over previous
#include <cuda_runtime.h>
#include <cuda_bf16.h>
#include <cuda_fp16.h>
#include <math_constants.h>
#include <stdint.h>

#define BATCH 4
#define NTOK 4096
#define CIN 256
#define ADIM 128
#define MTOT (BATCH*NTOK)
#define NEG_SLOPE 0.2f
#define LOG2E 1.4426950408889634f

// ---------------- scratch ----------------
__device__ __nv_bfloat16 g_Qh[MTOT * ADIM];   // pre-scaled by log2(e)
__device__ __nv_bfloat16 g_Ql[MTOT * ADIM];
__device__ __nv_bfloat16 g_Kh[MTOT * ADIM];
__device__ __nv_bfloat16 g_Kl[MTOT * ADIM];
__device__ __half        g_V[MTOT * ADIM];
__device__ __nv_bfloat16 g_Oh[MTOT * ADIM];
__device__ __nv_bfloat16 g_Ol[MTOT * ADIM];

__device__ __forceinline__ float lrelu(float x) { return x >= 0.0f ? x : NEG_SLOPE * x; }

// ---------------- helpers ----------------
__device__ __forceinline__ uint32_t smem_u32(const void* p) {
    uint32_t a;
    asm("{ .reg .u64 t; cvta.to.shared.u64 t, %1; cvt.u32.u64 %0, t; }" : "=r"(a) : "l"(p));
    return a;
}
__device__ __forceinline__ void cp16(uint32_t dst, const void* src) {
    asm volatile("cp.async.cg.shared.global [%0], [%1], 16;" :: "r"(dst), "l"(src));
}
__device__ __forceinline__ void cp_commit() { asm volatile("cp.async.commit_group;" ::: "memory"); }
__device__ __forceinline__ void cp_wait0() { asm volatile("cp.async.wait_group 0;" ::: "memory"); }
__device__ __forceinline__ void cp_wait1() { asm volatile("cp.async.wait_group 1;" ::: "memory"); }

__device__ __forceinline__ void ldsm4(uint32_t* r, uint32_t a) {
    asm volatile("ldmatrix.sync.aligned.m8n8.x4.shared.b16 {%0,%1,%2,%3}, [%4];"
        : "=r"(r[0]), "=r"(r[1]), "=r"(r[2]), "=r"(r[3]) : "r"(a));
}
__device__ __forceinline__ void ldsm4t(uint32_t* r, uint32_t a) {
    asm volatile("ldmatrix.sync.aligned.m8n8.x4.trans.shared.b16 {%0,%1,%2,%3}, [%4];"
        : "=r"(r[0]), "=r"(r[1]), "=r"(r[2]), "=r"(r[3]) : "r"(a));
}
__device__ __forceinline__ void mma_bf16(float* d, const uint32_t* a, const uint32_t* b) {
    asm volatile(
        "mma.sync.aligned.m16n8k16.row.col.f32.bf16.bf16.f32 "
        "{%0,%1,%2,%3}, {%4,%5,%6,%7}, {%8,%9}, {%0,%1,%2,%3};"
        : "+f"(d[0]), "+f"(d[1]), "+f"(d[2]), "+f"(d[3])
        : "r"(a[0]), "r"(a[1]), "r"(a[2]), "r"(a[3]), "r"(b[0]), "r"(b[1]));
}
__device__ __forceinline__ void mma_f16(float* d, const uint32_t* a, const uint32_t* b) {
    asm volatile(
        "mma.sync.aligned.m16n8k16.row.col.f32.f16.f16.f32 "
        "{%0,%1,%2,%3}, {%4,%5,%6,%7}, {%8,%9}, {%0,%1,%2,%3};"
        : "+f"(d[0]), "+f"(d[1]), "+f"(d[2]), "+f"(d[3])
        : "r"(a[0]), "r"(a[1]), "r"(a[2]), "r"(a[3]), "r"(b[0]), "r"(b[1]));
}
__device__ __forceinline__ uint32_t h2bits(__half2 v) { return *(uint32_t*)&v; }
__device__ __forceinline__ float ex2(float x) {
    float r; asm("ex2.approx.f32 %0, %1;" : "=f"(r) : "f"(x)); return r;
}

__device__ __forceinline__ void split2(float f0, float f1, __nv_bfloat162& h, __nv_bfloat162& l) {
    h = __floats2bfloat162_rn(f0, f1);
    l = __floats2bfloat162_rn(f0 - __bfloat162float(h.x), f1 - __bfloat162float(h.y));
}
// Convert 8 consecutive fp32 -> 16B hi chunk + 16B lo chunk, store to smem.
__device__ __forceinline__ void split_sts8(const float* src, uint32_t dst_h, uint32_t dst_l) {
    float4 a = *(const float4*)src;
    float4 b = *(const float4*)(src + 4);
    __nv_bfloat162 h0, l0, h1, l1, h2, l2, h3, l3;
    split2(a.x, a.y, h0, l0);
    split2(a.z, a.w, h1, l1);
    split2(b.x, b.y, h2, l2);
    split2(b.z, b.w, h3, l3);
    uint4 hv = make_uint4(*(uint32_t*)&h0, *(uint32_t*)&h1, *(uint32_t*)&h2, *(uint32_t*)&h3);
    uint4 lv = make_uint4(*(uint32_t*)&l0, *(uint32_t*)&l1, *(uint32_t*)&l2, *(uint32_t*)&l3);
    asm volatile("st.shared.v4.b32 [%0], {%1,%2,%3,%4};"
                 :: "r"(dst_h), "r"(hv.x), "r"(hv.y), "r"(hv.z), "r"(hv.w) : "memory");
    asm volatile("st.shared.v4.b32 [%0], {%1,%2,%3,%4};"
                 :: "r"(dst_l), "r"(lv.x), "r"(lv.y), "r"(lv.z), "r"(lv.w) : "memory");
}

// =====================================================================
// Kernel 1: QKV projection via mma.sync, 3xBF16 split.
// grid (128, 3), 256 threads. X and W loaded fp32, split inline (no
// converter kernels). Q scaled by log2(e); V emitted as single fp16.
// =====================================================================
#define QKV2_XH 0
#define QKV2_XL 16384
#define QKV2_WH 32768
#define QKV2_WL 49152
#define QKV2_SMEM 65536

__global__ __launch_bounds__(256)
void qkv2_kernel(const float* __restrict__ X,
                 const float* __restrict__ Wq,
                 const float* __restrict__ Wk,
                 const float* __restrict__ Wv) {
    extern __shared__ char smc[];
    const uint32_t sb = smem_u32(smc);
    const int tid = threadIdx.x;
    const int w = tid >> 5;
    const int lane = tid & 31;
    const int row0 = blockIdx.x * 128;

    const float* Wsel = (blockIdx.y == 0) ? Wq : (blockIdx.y == 1) ? Wk : Wv;

    const int rowa = 16 * w + (lane & 15);
    const int ca = lane >> 4, swa = rowa & 7;
    const int rowv = (lane & 7) + (lane & 8);
    const int cv = (lane >> 4) & 1, swv = rowv & 7;

    float oacc[16][4];
    #pragma unroll
    for (int nb = 0; nb < 16; nb++)
        #pragma unroll
        for (int i = 0; i < 4; i++) oacc[nb][i] = 0.0f;

    #pragma unroll 1
    for (int kc = 0; kc < 4; kc++) {
        __syncthreads();
        // X chunk [128 rows x 64 cols] fp32 -> hi/lo bf16 smem (swizzled)
        #pragma unroll
        for (int i = 0; i < 4; i++) {
            int lin = tid + i * 256;            // 1024 16B-chunks
            int r = lin >> 3, c = lin & 7;
            uint32_t off = (uint32_t)(r * 128 + ((c ^ (r & 7)) << 4));
            split_sts8(&X[(size_t)(row0 + r) * CIN + kc * 64 + c * 8],
                       sb + QKV2_XH + off, sb + QKV2_XL + off);
        }
        // W chunk [64 rows x 128 cols]
        #pragma unroll
        for (int i = 0; i < 4; i++) {
            int lin = tid + i * 256;
            int r = lin >> 4, c = lin & 15;
            uint32_t off = (uint32_t)(r * 256 + ((c ^ (r & 7)) << 4));
            split_sts8(&Wsel[(size_t)(kc * 64 + r) * ADIM + c * 8],
                       sb + QKV2_WH + off, sb + QKV2_WL + off);
        }
        __syncthreads();
        #pragma unroll
        for (int ks = 0; ks < 4; ks++) {
            uint32_t ah[4], al[4];
            uint32_t ach = (uint32_t)(((2 * ks + ca) ^ swa) << 4);
            ldsm4(ah, sb + QKV2_XH + rowa * 128 + ach);
            ldsm4(al, sb + QKV2_XL + rowa * 128 + ach);
            #pragma unroll
            for (int jp = 0; jp < 8; jp++) {
                uint32_t bh[4], bl[4];
                uint32_t boff = (uint32_t)((16 * ks + rowv) * 256 + (((2 * jp + cv) ^ swv) << 4));
                ldsm4t(bh, sb + QKV2_WH + boff);
                ldsm4t(bl, sb + QKV2_WL + boff);
                mma_bf16(oacc[2 * jp],     ah, bh); mma_bf16(oacc[2 * jp + 1], ah, bh + 2);
                mma_bf16(oacc[2 * jp],     ah, bl); mma_bf16(oacc[2 * jp + 1], ah, bl + 2);
                mma_bf16(oacc[2 * jp],     al, bh); mma_bf16(oacc[2 * jp + 1], al, bh + 2);
            }
        }
    }

    const int r0 = row0 + 16 * w + (lane >> 2);
    const int cb2 = 2 * (lane & 3);
    if (blockIdx.y == 2) {
        #pragma unroll
        for (int nb = 0; nb < 16; nb++) {
            int c = nb * 8 + cb2;
            *(__half2*)&g_V[(size_t)r0 * ADIM + c] =
                __floats2half2_rn(lrelu(oacc[nb][0]), lrelu(oacc[nb][1]));
            *(__half2*)&g_V[(size_t)(r0 + 8) * ADIM + c] =
                __floats2half2_rn(lrelu(oacc[nb][2]), lrelu(oacc[nb][3]));
        }
    } else {
        __nv_bfloat16* OH = (blockIdx.y == 0) ? g_Qh : g_Kh;
        __nv_bfloat16* OL = (blockIdx.y == 0) ? g_Ql : g_Kl;
        const float sc = (blockIdx.y == 0) ? LOG2E : 1.0f;
        #pragma unroll
        for (int nb = 0; nb < 16; nb++) {
            int c = nb * 8 + cb2;
            __nv_bfloat162 h01, l01, h23, l23;
            split2(lrelu(oacc[nb][0]) * sc, lrelu(oacc[nb][1]) * sc, h01, l01);
            split2(lrelu(oacc[nb][2]) * sc, lrelu(oacc[nb][3]) * sc, h23, l23);
            *(__nv_bfloat162*)&OH[(size_t)r0 * ADIM + c] = h01;
            *(__nv_bfloat162*)&OL[(size_t)r0 * ADIM + c] = l01;
            *(__nv_bfloat162*)&OH[(size_t)(r0 + 8) * ADIM + c] = h23;
            *(__nv_bfloat162*)&OL[(size_t)(r0 + 8) * ADIM + c] = l23;
        }
    }
}

// =====================================================================
// Kernel 2: flash attention, software-pipelined with double sacc.
// grid (32,4), 256 threads.  (unchanged from R11)
// smem: Qh 32K | Ql 32K | 3 x {Kh 16K | Kl 16K | V 16K} = 208K
// =====================================================================
#define SQH 0
#define SQL 32768
#define SKV 65536
#define KVBUF 49152
#define ATTN_SMEM (65536 + 3*KVBUF)

__device__ __forceinline__ void load_kv(uint32_t dst, const __nv_bfloat16* kh,
                                        const __nv_bfloat16* kl, const __half* v, int tid) {
    #pragma unroll
    for (int i = 0; i < 4; i++) {
        int lin = tid + i * 256;
        int r = lin >> 4, c = lin & 15;
        uint32_t off = (uint32_t)(r * 256 + ((c ^ (r & 7)) << 4));
        size_t g = (size_t)r * ADIM + c * 8;
        cp16(dst + off, kh + g);
        cp16(dst + 16384 + off, kl + g);
        cp16(dst + 32768 + off, v + g);
    }
}

__global__ __launch_bounds__(256, 1)
void attn_kernel() {
    extern __shared__ char smc[];
    const uint32_t sb = smem_u32(smc);
    const int tid = threadIdx.x;
    const int w = tid >> 5;
    const int lane = tid & 31;
    const int b = blockIdx.y;
    const int q0 = blockIdx.x * 128;

    const int rowa = 16 * w + (lane & 15);
    const uint32_t qro = (uint32_t)rowa * 256;
    const int ca = lane >> 4;
    const int swa = rowa & 7;
    const int rowb = (lane & 7) + ((lane & 16) >> 1);
    const int cb = (lane >> 3) & 1;
    const int swb = rowb & 7;
    const int rowv = (lane & 7) + (lane & 8);
    const int cv = (lane >> 4) & 1;
    const int swv = rowv & 7;

    // ---- prologue ----
    {
        const __nv_bfloat16* qh = g_Qh + (size_t)(b * NTOK + q0) * ADIM;
        const __nv_bfloat16* ql = g_Ql + (size_t)(b * NTOK + q0) * ADIM;
        #pragma unroll
        for (int i = 0; i < 8; i++) {
            int lin = tid + i * 256;
            int r = lin >> 4, c = lin & 15;
            uint32_t off = (uint32_t)(r * 256 + ((c ^ (r & 7)) << 4));
            size_t g = (size_t)r * ADIM + c * 8;
            cp16(sb + SQH + off, qh + g);
            cp16(sb + SQL + off, ql + g);
        }
    }
    const __nv_bfloat16* KHb = g_Kh + (size_t)b * NTOK * ADIM;
    const __nv_bfloat16* KLb = g_Kl + (size_t)b * NTOK * ADIM;
    const __half* Vb = g_V + (size_t)b * NTOK * ADIM;
    load_kv(sb + SKV, KHb, KLb, Vb, tid);
    cp_commit();
    load_kv(sb + SKV + KVBUF, KHb + 64 * ADIM, KLb + 64 * ADIM, Vb + 64 * ADIM, tid);
    cp_commit();
    cp_wait1();
    __syncthreads();

    float oacc[16][4];
    #pragma unroll
    for (int nb = 0; nb < 16; nb++)
        #pragma unroll
        for (int i = 0; i < 4; i++) oacc[nb][i] = 0.0f;
    float m0 = -CUDART_INF_F, m8 = -CUDART_INF_F, l0 = 0.0f, l8 = 0.0f;

    float sA[8][4], sB[8][4];

    auto s_mma = [&](float (&sacc)[8][4], uint32_t KB) {
        #pragma unroll
        for (int nb = 0; nb < 8; nb++)
            #pragma unroll
            for (int i = 0; i < 4; i++) sacc[nb][i] = 0.0f;
        #pragma unroll
        for (int ks = 0; ks < 8; ks++) {
            uint32_t aqh[4], aql[4];
            uint32_t ach = (uint32_t)(((2 * ks + ca) ^ swa) << 4);
            ldsm4(aqh, sb + SQH + qro + ach);
            ldsm4(aql, sb + SQL + qro + ach);
            uint32_t bch = (uint32_t)(((2 * ks + cb) ^ swb) << 4);
            #pragma unroll
            for (int jp = 0; jp < 4; jp++) {
                uint32_t bh[4], bl[4];
                uint32_t boff = (uint32_t)((16 * jp + rowb) * 256) + bch;
                ldsm4(bh, KB + boff);
                ldsm4(bl, KB + 16384u + boff);
                mma_bf16(sacc[2 * jp],     aqh, bh);
                mma_bf16(sacc[2 * jp + 1], aqh, bh + 2);
                mma_bf16(sacc[2 * jp],     aqh, bl);
                mma_bf16(sacc[2 * jp + 1], aqh, bl + 2);
                mma_bf16(sacc[2 * jp],     aql, bh);
                mma_bf16(sacc[2 * jp + 1], aql, bh + 2);
            }
        }
    };

    auto softmax_pv = [&](float (&sacc)[8][4], uint32_t VB) {
        float rm0 = sacc[0][0], rm8 = sacc[0][2];
        #pragma unroll
        for (int nb = 0; nb < 8; nb++) {
            rm0 = fmaxf(rm0, fmaxf(sacc[nb][0], sacc[nb][1]));
            rm8 = fmaxf(rm8, fmaxf(sacc[nb][2], sacc[nb][3]));
        }
        rm0 = fmaxf(rm0, __shfl_xor_sync(0xffffffffu, rm0, 1));
        rm0 = fmaxf(rm0, __shfl_xor_sync(0xffffffffu, rm0, 2));
        rm8 = fmaxf(rm8, __shfl_xor_sync(0xffffffffu, rm8, 1));
        rm8 = fmaxf(rm8, __shfl_xor_sync(0xffffffffu, rm8, 2));
        float mn0 = fmaxf(m0, rm0), mn8 = fmaxf(m8, rm8);
        float sc0 = ex2(m0 - mn0), sc8 = ex2(m8 - mn8);
        m0 = mn0; m8 = mn8;

        uint32_t ph[8][2];
        float ls0 = 0.0f, ls8 = 0.0f;
        #pragma unroll
        for (int nb = 0; nb < 8; nb++) {
            float p0 = ex2(sacc[nb][0] - mn0);
            float p1 = ex2(sacc[nb][1] - mn0);
            float p2 = ex2(sacc[nb][2] - mn8);
            float p3 = ex2(sacc[nb][3] - mn8);
            ls0 += p0 + p1; ls8 += p2 + p3;
            ph[nb][0] = h2bits(__floats2half2_rn(p0, p1));
            ph[nb][1] = h2bits(__floats2half2_rn(p2, p3));
        }
        l0 = l0 * sc0 + ls0;
        l8 = l8 * sc8 + ls8;
        if (sc0 < 1.0f) {
            #pragma unroll
            for (int nb = 0; nb < 16; nb++) { oacc[nb][0] *= sc0; oacc[nb][1] *= sc0; }
        }
        if (sc8 < 1.0f) {
            #pragma unroll
            for (int nb = 0; nb < 16; nb++) { oacc[nb][2] *= sc8; oacc[nb][3] *= sc8; }
        }

        #pragma unroll
        for (int ks = 0; ks < 4; ks++) {
            uint32_t ah[4] = { ph[2 * ks][0], ph[2 * ks][1], ph[2 * ks + 1][0], ph[2 * ks + 1][1] };
            uint32_t vro = (uint32_t)((16 * ks + rowv) * 256);
            #pragma unroll
            for (int jp = 0; jp < 8; jp++) {
                uint32_t bh[4];
                uint32_t voff = vro + (uint32_t)(((2 * jp + cv) ^ swv) << 4);
                ldsm4t(bh, VB + voff);
                mma_f16(oacc[2 * jp],     ah, bh);
                mma_f16(oacc[2 * jp + 1], ah, bh + 2);
            }
        }
    };

    auto kbuf = [&](int i) { return sb + SKV + (uint32_t)(i % 3) * (uint32_t)KVBUF; };
    auto vbuf = [&](int i) { return sb + SKV + (uint32_t)(i % 3) * (uint32_t)KVBUF + 32768u; };

    s_mma(sA, kbuf(0));

    #pragma unroll 1
    for (int t = 0; t < 64; t += 2) {
        if (t < 63) cp_wait0();
        __syncthreads();
        if (t < 63) s_mma(sB, kbuf(t + 1));
        if (t < 62) {
            size_t o = (size_t)(t + 2) * 64 * ADIM;
            load_kv(kbuf(t + 2), KHb + o, KLb + o, Vb + o, tid);
            cp_commit();
        }
        softmax_pv(sA, vbuf(t));

        const int u = t + 1;
        if (u < 63) cp_wait0();
        __syncthreads();
        if (u < 63) s_mma(sA, kbuf(u + 1));
        if (u < 62) {
            size_t o = (size_t)(u + 2) * 64 * ADIM;
            load_kv(kbuf(u + 2), KHb + o, KLb + o, Vb + o, tid);
            cp_commit();
        }
        softmax_pv(sB, vbuf(u));
    }

    // ---- epilogue ----
    l0 += __shfl_xor_sync(0xffffffffu, l0, 1);
    l0 += __shfl_xor_sync(0xffffffffu, l0, 2);
    l8 += __shfl_xor_sync(0xffffffffu, l8, 1);
    l8 += __shfl_xor_sync(0xffffffffu, l8, 2);
    float inv0 = 1.0f / l0, inv8 = 1.0f / l8;
    size_t r0 = (size_t)b * NTOK + q0 + 16 * w + (lane >> 2);
    int cb2 = 2 * (lane & 3);
    #pragma unroll
    for (int nb = 0; nb < 16; nb++) {
        int c = nb * 8 + cb2;
        __nv_bfloat162 h01, l01, h23, l23;
        split2(oacc[nb][0] * inv0, oacc[nb][1] * inv0, h01, l01);
        split2(oacc[nb][2] * inv8, oacc[nb][3] * inv8, h23, l23);
        *(__nv_bfloat162*)&g_Oh[r0 * ADIM + c] = h01;
        *(__nv_bfloat162*)&g_Ol[r0 * ADIM + c] = l01;
        *(__nv_bfloat162*)&g_Oh[(r0 + 8) * ADIM + c] = h23;
        *(__nv_bfloat162*)&g_Ol[(r0 + 8) * ADIM + c] = l23;
    }
}

// =====================================================================
// Kernel 3: Y = O @ Wo * tanh(relu(1+wg)) via mma.sync, 3xBF16 split.
// grid (128, 2), 256 threads. Wo loaded fp32, split inline (overlaps
// the cp.async of O).
// =====================================================================
#define OUT2_AH 0
#define OUT2_AL 16384
#define OUT2_WH 32768
#define OUT2_WL 49152
#define OUT2_SMEM 65536

__global__ __launch_bounds__(256)
void out2_kernel(const float* __restrict__ Wo,
                 const float* __restrict__ wgm, float* __restrict__ Y) {
    extern __shared__ char smc[];
    const uint32_t sb = smem_u32(smc);
    const int tid = threadIdx.x;
    const int w = tid >> 5;
    const int lane = tid & 31;
    const int row0 = blockIdx.x * 128;
    const int col0 = blockIdx.y * 128;

    const int rowa = 16 * w + (lane & 15);
    const int ca = lane >> 4, swa = rowa & 7;
    const int rowv = (lane & 7) + (lane & 8);
    const int cv = (lane >> 4) & 1, swv = rowv & 7;

    float oacc[16][4];
    #pragma unroll
    for (int nb = 0; nb < 16; nb++)
        #pragma unroll
        for (int i = 0; i < 4; i++) oacc[nb][i] = 0.0f;

    #pragma unroll 1
    for (int kc = 0; kc < 2; kc++) {
        __syncthreads();
        // O chunk [128 x 64] via cp.async (bf16 hi/lo in gmem)
        #pragma unroll
        for (int i = 0; i < 4; i++) {
            int lin = tid + i * 256;
            int r = lin >> 3, c = lin & 7;
            uint32_t off = (uint32_t)(r * 128 + ((c ^ (r & 7)) << 4));
            size_t g = (size_t)(row0 + r) * ADIM + kc * 64 + c * 8;
            cp16(sb + OUT2_AH + off, g_Oh + g);
            cp16(sb + OUT2_AL + off, g_Ol + g);
        }
        cp_commit();
        // Wo chunk [64 x 128] fp32 -> split inline (overlaps cp.async)
        #pragma unroll
        for (int i = 0; i < 4; i++) {
            int lin = tid + i * 256;
            int r = lin >> 4, c = lin & 15;
            uint32_t off = (uint32_t)(r * 256 + ((c ^ (r & 7)) << 4));
            split_sts8(&Wo[(size_t)(kc * 64 + r) * CIN + col0 + c * 8],
                       sb + OUT2_WH + off, sb + OUT2_WL + off);
        }
        cp_wait0();
        __syncthreads();
        #pragma unroll
        for (int ks = 0; ks < 4; ks++) {
            uint32_t ah[4], al[4];
            uint32_t ach = (uint32_t)(((2 * ks + ca) ^ swa) << 4);
            ldsm4(ah, sb + OUT2_AH + rowa * 128 + ach);
            ldsm4(al, sb + OUT2_AL + rowa * 128 + ach);
            #pragma unroll
            for (int jp = 0; jp < 8; jp++) {
                uint32_t bh[4], bl[4];
                uint32_t boff = (uint32_t)((16 * ks + rowv) * 256 + (((2 * jp + cv) ^ swv) << 4));
                ldsm4t(bh, sb + OUT2_WH + boff);
                ldsm4t(bl, sb + OUT2_WL + boff);
                mma_bf16(oacc[2 * jp],     ah, bh); mma_bf16(oacc[2 * jp + 1], ah, bh + 2);
                mma_bf16(oacc[2 * jp],     ah, bl); mma_bf16(oacc[2 * jp + 1], ah, bl + 2);
                mma_bf16(oacc[2 * jp],     al, bh); mma_bf16(oacc[2 * jp + 1], al, bh + 2);
            }
        }
    }

    const int r0 = row0 + 16 * w + (lane >> 2);
    const int cb2 = 2 * (lane & 3);
    #pragma unroll
    for (int nb = 0; nb < 16; nb++) {
        int c = col0 + nb * 8 + cb2;
        float g0 = tanhf(fmaxf(1.0f + wgm[c], 0.0f));
        float g1 = tanhf(fmaxf(1.0f + wgm[c + 1], 0.0f));
        *(float2*)&Y[(size_t)r0 * CIN + c] =
            make_float2(oacc[nb][0] * g0, oacc[nb][1] * g1);
        *(float2*)&Y[(size_t)(r0 + 8) * CIN + c] =
            make_float2(oacc[nb][2] * g0, oacc[nb][3] * g1);
    }
}

// =====================================================================
extern "C" void kernel_launch(void* const* d_in, const int* in_sizes, int n_in,
                              void* d_out, int out_size) {
    const float* x  = (const float*)d_in[0];
    const float* Wq = (const float*)d_in[1];
    const float* Wk = (const float*)d_in[2];
    const float* Wv = (const float*)d_in[3];
    const float* Wo = (const float*)d_in[4];
    const float* wg = (const float*)d_in[5];
    float* y = (float*)d_out;

    static bool attrs_set = []() {
        cudaFuncSetAttribute(qkv2_kernel, cudaFuncAttributeMaxDynamicSharedMemorySize, QKV2_SMEM);
        cudaFuncSetAttribute(attn_kernel, cudaFuncAttributeMaxDynamicSharedMemorySize, ATTN_SMEM);
        cudaFuncSetAttribute(out2_kernel, cudaFuncAttributeMaxDynamicSharedMemorySize, OUT2_SMEM);
        return true;
    }();
    (void)attrs_set;

    qkv2_kernel<<<dim3(128, 3), 256, QKV2_SMEM>>>(x, Wq, Wk, Wv);
    attn_kernel<<<dim3(NTOK / 128, BATCH), 256, ATTN_SMEM>>>();
    out2_kernel<<<dim3(128, 2), 256, OUT2_SMEM>>>(Wo, wg, y);
}